// round 1
// baseline (speedup 1.0000x reference)
#include <cuda_runtime.h>
#include <math.h>

#define BATCH 2
#define C 192
#define HH 256
#define WW 256
#define HW (HH*WW)
#define NPIX (BATCH*HW)
#define NH 8
#define HD 24
#define WS 8
#define SS 4
#define HID 510
#define HID2 1020

// ---- scratch (static device globals; no cudaMalloc allowed) ----
__device__ float g_xn[NPIX*C];            // LN1 output (BHWC)
__device__ float g_xt[NPIX*C];            // x transposed to BHWC (residual)
__device__ float g_x2[NPIX*C];            // x + attn (BHWC)
__device__ float g_yn[NPIX*C];            // LN2 output (BHWC)
__device__ float g_y [(size_t)NPIX*HID2]; // pin output (pix-major, 1020 ch)
__device__ float g_g [(size_t)NPIX*HID];  // gated gelu output

// ================= K1: LN1 + transpose ==================
__global__ __launch_bounds__(256) void k_ln1(const float* __restrict__ x,
        const float* __restrict__ w, const float* __restrict__ b) {
    __shared__ float s[C*33];
    __shared__ float smu[32], srv[32];
    int pix0 = blockIdx.x * 32;
    int bb = pix0 / HW;
    int hw0 = pix0 % HW;
    for (int e = threadIdx.x; e < C*32; e += 256) {
        int c = e >> 5, p = e & 31;
        s[c*33 + p] = x[(size_t)(bb*C + c)*HW + hw0 + p];
    }
    __syncthreads();
    if (threadIdx.x < 32) {
        int p = threadIdx.x;
        float sum = 0.f, sq = 0.f;
        for (int c = 0; c < C; c++) { float v = s[c*33+p]; sum += v; sq += v*v; }
        float mu = sum / C;
        float var = sq / C - mu*mu;
        smu[p] = mu; srv[p] = rsqrtf(var + 1e-5f);
    }
    __syncthreads();
    for (int e = threadIdx.x; e < C*32; e += 256) {
        int p = e / C, c = e % C;
        float v = s[c*33 + p];
        int gi = (pix0 + p)*C + c;
        g_xt[gi] = v;
        g_xn[gi] = (v - smu[p]) * srv[p] * w[c] + b[c];
    }
}

// ================= K2: fused window attention ==================
#define SQ 196   // token-major row stride for Q/K/V/O (mult of 4)
#define XT 68    // k-major stride for XsT / As / Bs
__global__ __launch_bounds__(256,1) void k_attn(
    const float* __restrict__ qkv_w, const float* __restrict__ rpb,
    const float* __restrict__ proj_w, const float* __restrict__ proj_b)
{
    extern __shared__ float sm[];
    float* XsT = sm;                 // [192][68] (k-major input); later O [64][196]
    float* Qs  = sm + 192*XT;        // [64][196]
    float* Ks  = Qs + 64*SQ;
    float* Vs  = Ks + 64*SQ;
    float* As  = Vs + 64*SQ;         // [64][68] attn scores; also weight tile Bs
    float* Bs  = As;
    __shared__ int lab[64];
    __shared__ int gbase[64];

    int tid = threadIdx.x;
    int bb = blockIdx.x >> 10;
    int wy = (blockIdx.x >> 5) & 31;
    int wx = blockIdx.x & 31;

    if (tid < 64) {
        int i1 = tid >> 3, j1 = tid & 7;
        int sr = wy*8 + i1, sc = wx*8 + j1;
        lab[tid] = ((sr >= HH-WS) + (sr >= HH-SS))*3 + ((sc >= WW-WS) + (sc >= WW-SS));
        int r = (sr + SS) & (HH-1), c2 = (sc + SS) & (WW-1);
        gbase[tid] = ((bb*HH + r)*WW + c2)*C;
    }
    __syncthreads();
    for (int e = tid; e < 64*C; e += 256) {
        int n = e / C, c = e % C;
        XsT[c*XT + n] = g_xn[gbase[n] + c];
    }
    __syncthreads();

    int tx = tid & 15, ty = tid >> 4;
    const float qscale = 0.20412414523193154f;  // 24^-0.5

    // ---- QKV GEMM: 64 tok x 576 out, K=192 ----
    for (int dt = 0; dt < 9; dt++) {
        float acc[4][4] = {};
        for (int k0 = 0; k0 < C; k0 += 32) {
            __syncthreads();
            for (int e = tid; e < 2048; e += 256) {
                int o = e >> 5, kk = e & 31;
                Bs[kk*XT + o] = qkv_w[(dt*64 + o)*C + k0 + kk];
            }
            __syncthreads();
            #pragma unroll
            for (int kk = 0; kk < 32; kk++) {
                float4 xv = *(const float4*)&XsT[(k0+kk)*XT + ty*4];
                float4 wv = *(const float4*)&Bs[kk*XT + tx*4];
                float xa[4] = {xv.x,xv.y,xv.z,xv.w};
                float wa[4] = {wv.x,wv.y,wv.z,wv.w};
                #pragma unroll
                for (int i=0;i<4;i++)
                    #pragma unroll
                    for (int j=0;j<4;j++)
                        acc[i][j] += xa[i]*wa[j];
            }
        }
        __syncthreads();
        #pragma unroll
        for (int i=0;i<4;i++) {
            int n = ty*4 + i;
            #pragma unroll
            for (int j=0;j<4;j++) {
                int d = dt*64 + tx*4 + j;
                float v = acc[i][j];
                if (d < C)        Qs[n*SQ + d] = v * qscale;
                else if (d < 2*C) Ks[n*SQ + (d - C)] = v;
                else              Vs[n*SQ + (d - 2*C)] = v;
            }
        }
    }
    __syncthreads();

    // ---- per-head attention ----
    for (int h = 0; h < NH; h++) {
        int off = h*HD;
        {   // QK^T + bias + mask : thread computes 4n x 4m
            int m0 = tx*4, n0 = ty*4;
            float a[4][4] = {};
            #pragma unroll
            for (int d4 = 0; d4 < 6; d4++) {
                float4 q[4], kv[4];
                #pragma unroll
                for (int i=0;i<4;i++) q[i] = *(const float4*)&Qs[(n0+i)*SQ + off + d4*4];
                #pragma unroll
                for (int j=0;j<4;j++) kv[j] = *(const float4*)&Ks[(m0+j)*SQ + off + d4*4];
                #pragma unroll
                for (int i=0;i<4;i++)
                  #pragma unroll
                  for (int j=0;j<4;j++)
                    a[i][j] += q[i].x*kv[j].x + q[i].y*kv[j].y + q[i].z*kv[j].z + q[i].w*kv[j].w;
            }
            #pragma unroll
            for (int i=0;i<4;i++) {
                int n = n0+i; int i1 = n>>3, j1 = n&7;
                #pragma unroll
                for (int j=0;j<4;j++) {
                    int m = m0+j; int i2 = m>>3, j2 = m&7;
                    float v = a[i][j] + rpb[((i1-i2+7)*15 + (j1-j2+7))*NH + h];
                    if (lab[n] != lab[m]) v -= 100.f;
                    As[n*XT + m] = v;
                }
            }
        }
        __syncthreads();
        if (tid < 64) {   // softmax per row
            float* row = &As[tid*XT];
            float mx = row[0];
            #pragma unroll
            for (int m=1;m<64;m++) mx = fmaxf(mx, row[m]);
            float s2 = 0.f;
            for (int m=0;m<64;m++) { float e2 = expf(row[m]-mx); row[m]=e2; s2+=e2; }
            float inv = 1.f/s2;
            for (int m=0;m<64;m++) row[m] *= inv;
        }
        __syncthreads();
        // AV -> O (stored in XsT region, token-major stride SQ)
        for (int e = tid; e < 64*6; e += 256) {
            int n = e / 6, d4 = e % 6;
            float4 acc = make_float4(0.f,0.f,0.f,0.f);
            const float* arow = &As[n*XT];
            #pragma unroll 8
            for (int m=0;m<64;m++) {
                float a = arow[m];
                float4 v = *(const float4*)&Vs[m*SQ + off + d4*4];
                acc.x += a*v.x; acc.y += a*v.y; acc.z += a*v.z; acc.w += a*v.w;
            }
            *(float4*)&XsT[n*SQ + off + d4*4] = acc;
        }
        __syncthreads();
    }

    // ---- proj + residual -> g_x2 ----
    float* O = XsT;
    for (int dt = 0; dt < 3; dt++) {
        float acc[4][4] = {};
        for (int k0 = 0; k0 < C; k0 += 32) {
            __syncthreads();
            for (int e = tid; e < 2048; e += 256) {
                int o = e >> 5, kk = e & 31;
                Bs[o*36 + kk] = proj_w[(dt*64 + o)*C + k0 + kk];
            }
            __syncthreads();
            #pragma unroll
            for (int k4 = 0; k4 < 8; k4++) {
                float4 ov[4], wv[4];
                #pragma unroll
                for (int i=0;i<4;i++) ov[i] = *(const float4*)&O[(ty*4+i)*SQ + k0 + k4*4];
                #pragma unroll
                for (int j=0;j<4;j++) wv[j] = *(const float4*)&Bs[(tx*4+j)*36 + k4*4];
                #pragma unroll
                for (int i=0;i<4;i++)
                  #pragma unroll
                  for (int j=0;j<4;j++)
                    acc[i][j] += ov[i].x*wv[j].x + ov[i].y*wv[j].y + ov[i].z*wv[j].z + ov[i].w*wv[j].w;
            }
        }
        #pragma unroll
        for (int i=0;i<4;i++) {
            int n = ty*4 + i;
            #pragma unroll
            for (int j=0;j<4;j++) {
                int c = dt*64 + tx*4 + j;
                int gi = gbase[n] + c;
                g_x2[gi] = g_xt[gi] + acc[i][j] + proj_b[c];
            }
        }
    }
}

// ================= K3: LN2 ==================
__global__ __launch_bounds__(256) void k_ln2(const float* __restrict__ w,
                                             const float* __restrict__ b) {
    int pix = blockIdx.x*8 + (threadIdx.x >> 5);
    int lane = threadIdx.x & 31;
    const float* row = g_x2 + (size_t)pix*C;
    float v[6];
    float sum = 0.f, sq = 0.f;
    #pragma unroll
    for (int i=0;i<6;i++) { v[i] = row[lane + 32*i]; sum += v[i]; sq += v[i]*v[i]; }
    #pragma unroll
    for (int o=16;o;o>>=1) { sum += __shfl_xor_sync(0xffffffffu,sum,o);
                             sq  += __shfl_xor_sync(0xffffffffu,sq ,o); }
    float mu = sum / C;
    float rv = rsqrtf(sq / C - mu*mu + 1e-5f);
    float* outp = g_yn + (size_t)pix*C;
    #pragma unroll
    for (int i=0;i<6;i++) { int c = lane + 32*i; outp[c] = (v[i]-mu)*rv*w[c] + b[c]; }
}

// ================= K4: pin GEMM (131072 x 1020 x 192) ==================
__global__ __launch_bounds__(256) void k_pin(const float* __restrict__ pw) {
    __shared__ float As[32*132];   // [kk][pix] 128-wide
    __shared__ float Bs[32*68];    // [kk][o]   64-wide
    int pt = blockIdx.y * 128;
    int ot = blockIdx.x * 64;
    int tid = threadIdx.x;
    int tx = tid & 15, ty = tid >> 4;
    float acc[8][4] = {};
    for (int k0 = 0; k0 < C; k0 += 32) {
        __syncthreads();
        for (int e = tid; e < 4096; e += 256) {
            int r = e >> 5, kk = e & 31;
            As[kk*132 + r] = g_yn[(size_t)(pt + r)*C + k0 + kk];
        }
        for (int e = tid; e < 2048; e += 256) {
            int o = e >> 5, kk = e & 31;
            int og = ot + o;
            Bs[kk*68 + o] = (og < HID2) ? pw[og*C + k0 + kk] : 0.f;
        }
        __syncthreads();
        #pragma unroll
        for (int kk = 0; kk < 32; kk++) {
            float4 a0 = *(const float4*)&As[kk*132 + ty*8];
            float4 a1 = *(const float4*)&As[kk*132 + ty*8 + 4];
            float4 b  = *(const float4*)&Bs[kk*68 + tx*4];
            float av[8] = {a0.x,a0.y,a0.z,a0.w,a1.x,a1.y,a1.z,a1.w};
            float bv[4] = {b.x,b.y,b.z,b.w};
            #pragma unroll
            for (int i=0;i<8;i++)
              #pragma unroll
              for (int j=0;j<4;j++)
                acc[i][j] += av[i]*bv[j];
        }
    }
    #pragma unroll
    for (int i=0;i<8;i++) {
        size_t pix = pt + ty*8 + i;
        int o = ot + tx*4;
        float* dst = &g_y[pix*HID2 + o];
        if (o + 3 < HID2) {
            *(float4*)dst = make_float4(acc[i][0],acc[i][1],acc[i][2],acc[i][3]);
        } else {
            #pragma unroll
            for (int j=0;j<4;j++) if (o + j < HID2) dst[j] = acc[i][j];
        }
    }
}

// ================= K5: depthwise 3x3 + gated GELU ==================
__global__ __launch_bounds__(256) void k_dw(const float* __restrict__ dw) {
    int bx = blockIdx.x;               // B * H * (W/4) = 32768
    int c = blockIdx.y * 256 + threadIdx.x;
    if (c >= HID) return;
    int xseg = (bx & 63) * 4;
    int r = (bx >> 6) & 255;
    int bb = bx >> 14;
    float ya[3][6], yb[3][6];
    #pragma unroll
    for (int dy = 0; dy < 3; dy++) {
        int rowi = r + dy - 1;
        bool rok = (unsigned)rowi < 256u;
        #pragma unroll
        for (int dx = 0; dx < 6; dx++) {
            int col = xseg + dx - 1;
            bool ok = rok && ((unsigned)col < 256u);
            size_t base = ((size_t)(bb*HH + rowi)*WW + col)*HID2;
            ya[dy][dx] = ok ? g_y[base + c] : 0.f;
            yb[dy][dx] = ok ? g_y[base + c + HID] : 0.f;
        }
    }
    float wa[9], wb[9];
    #pragma unroll
    for (int t = 0; t < 9; t++) { wa[t] = dw[c*9 + t]; wb[t] = dw[(c + HID)*9 + t]; }
    #pragma unroll
    for (int o = 0; o < 4; o++) {
        float a = 0.f, g2 = 0.f;
        #pragma unroll
        for (int ky = 0; ky < 3; ky++)
          #pragma unroll
          for (int kx = 0; kx < 3; kx++) {
            a  += wa[ky*3+kx] * ya[ky][o+kx];
            g2 += wb[ky*3+kx] * yb[ky][o+kx];
          }
        float ge = 0.5f * a * (1.f + erff(a * 0.70710678118654752f));
        g_g[((size_t)(bb*HH + r)*WW + xseg + o)*HID + c] = ge * g2;
    }
}

// ================= K6: pout GEMM + residual -> NCHW output ==================
__global__ __launch_bounds__(256) void k_pout(const float* __restrict__ pw,
                                              float* __restrict__ outp) {
    __shared__ float As[32*68];    // [kk][pix]
    __shared__ float Bs[32*68];    // [kk][c]
    __shared__ float Xs2[64*68];   // [c][pix]
    int pt = blockIdx.y * 64;
    int ct = blockIdx.x * 64;
    int tid = threadIdx.x;
    int tx = tid & 15, ty = tid >> 4;   // tx -> pix, ty -> c
    float acc[4][4] = {};               // [c][pix]
    for (int k0 = 0; k0 < HID; k0 += 32) {
        __syncthreads();
        int kmax = HID - k0;
        for (int e = tid; e < 2048; e += 256) {
            int r = e >> 5, kk = e & 31;
            bool ok = kk < kmax;
            As[kk*68 + r] = ok ? g_g[(size_t)(pt + r)*HID + k0 + kk] : 0.f;
            Bs[kk*68 + r] = ok ? pw[(ct + r)*HID + k0 + kk] : 0.f;
        }
        __syncthreads();
        #pragma unroll
        for (int kk = 0; kk < 32; kk++) {
            float4 a = *(const float4*)&As[kk*68 + tx*4];
            float4 b = *(const float4*)&Bs[kk*68 + ty*4];
            float av[4] = {a.x,a.y,a.z,a.w};
            float bv[4] = {b.x,b.y,b.z,b.w};
            #pragma unroll
            for (int j=0;j<4;j++)
              #pragma unroll
              for (int i=0;i<4;i++)
                acc[j][i] += bv[j]*av[i];
        }
    }
    __syncthreads();
    for (int e = tid; e < 4096; e += 256) {
        int p = e >> 6, c = e & 63;
        Xs2[c*68 + p] = g_x2[(size_t)(pt + p)*C + ct + c];
    }
    __syncthreads();
    int bb = pt >> 16;
    int hw0 = (pt & 65535) + tx*4;
    #pragma unroll
    for (int j = 0; j < 4; j++) {
        int c = ct + ty*4 + j;
        const float* xp = &Xs2[(ty*4+j)*68 + tx*4];
        float4 v = make_float4(acc[j][0] + xp[0], acc[j][1] + xp[1],
                               acc[j][2] + xp[2], acc[j][3] + xp[3]);
        *(float4*)&outp[((size_t)(bb*C + c))*HW + hw0] = v;
    }
}

// ================= launch ==================
extern "C" void kernel_launch(void* const* d_in, const int* in_sizes, int n_in,
                              void* d_out, int out_size) {
    const float* x      = (const float*)d_in[0];
    const float* n1w    = (const float*)d_in[1];
    const float* n1b    = (const float*)d_in[2];
    const float* qkv_w  = (const float*)d_in[3];
    const float* rpb    = (const float*)d_in[4];
    const float* proj_w = (const float*)d_in[5];
    const float* proj_b = (const float*)d_in[6];
    const float* n2w    = (const float*)d_in[7];
    const float* n2b    = (const float*)d_in[8];
    const float* pin_w  = (const float*)d_in[9];
    const float* dw_w   = (const float*)d_in[10];
    const float* pout_w = (const float*)d_in[11];
    float* outp = (float*)d_out;

    const int attn_smem = (192*XT + 3*64*SQ + 64*XT) * 4;   // 220160 B
    cudaFuncSetAttribute(k_attn, cudaFuncAttributeMaxDynamicSharedMemorySize, attn_smem);

    k_ln1 <<<NPIX/32, 256>>>(x, n1w, n1b);
    k_attn<<<2048, 256, attn_smem>>>(qkv_w, rpb, proj_w, proj_b);
    k_ln2 <<<NPIX/8, 256>>>(n2w, n2b);
    k_pin <<<dim3(16, NPIX/128), 256>>>(pin_w);
    k_dw  <<<dim3(BATCH*HH*(WW/4), 2), 256>>>(dw_w);
    k_pout<<<dim3(3, NPIX/64), 256>>>(pout_w, outp);
}

// round 3
// speedup vs baseline: 1.1342x; 1.1342x over previous
#include <cuda_runtime.h>
#include <math.h>

#define BATCH 2
#define C 192
#define HH 256
#define WW 256
#define HW (HH*WW)
#define NPIX (BATCH*HW)
#define NH 8
#define HD 24
#define WS 8
#define SS 4
#define HID 510
#define HID2 1020

// ---- scratch (static device globals; no cudaMalloc allowed) ----
__device__ float g_xn[NPIX*C];            // LN1 output (BHWC)
__device__ float g_xt[NPIX*C];            // x transposed to BHWC (residual)
__device__ float g_x2[NPIX*C];            // x + attn (BHWC)
__device__ float g_yn[NPIX*C];            // LN2 output (BHWC)
__device__ float g_y [(size_t)NPIX*HID2]; // pin output (pix-major, 1020 ch)
__device__ float g_g [(size_t)NPIX*HID];  // gated gelu output

__device__ __forceinline__ float to_tf32(float x) {
    float r; asm("cvt.rna.tf32.f32 %0, %1;" : "=f"(r) : "f"(x)); return r;
}

__device__ __forceinline__ void mma_tf32(float& c0, float& c1, float& c2, float& c3,
    float a0, float a1, float a2, float a3, float b0, float b1) {
    asm volatile("mma.sync.aligned.m16n8k8.row.col.f32.tf32.tf32.f32 "
        "{%0,%1,%2,%3}, {%4,%5,%6,%7}, {%8,%9}, {%0,%1,%2,%3};"
        : "+f"(c0), "+f"(c1), "+f"(c2), "+f"(c3)
        : "r"(__float_as_uint(a0)), "r"(__float_as_uint(a1)),
          "r"(__float_as_uint(a2)), "r"(__float_as_uint(a3)),
          "r"(__float_as_uint(b0)), "r"(__float_as_uint(b1)));
}

// ================= K1: LN1 + transpose ==================
__global__ __launch_bounds__(256) void k_ln1(const float* __restrict__ x,
        const float* __restrict__ w, const float* __restrict__ b) {
    __shared__ float s[C*33];
    __shared__ float smu[32], srv[32];
    int pix0 = blockIdx.x * 32;
    int bb = pix0 / HW;
    int hw0 = pix0 % HW;
    for (int e = threadIdx.x; e < C*32; e += 256) {
        int c = e >> 5, p = e & 31;
        s[c*33 + p] = x[(size_t)(bb*C + c)*HW + hw0 + p];
    }
    __syncthreads();
    if (threadIdx.x < 32) {
        int p = threadIdx.x;
        float sum = 0.f, sq = 0.f;
        for (int c = 0; c < C; c++) { float v = s[c*33+p]; sum += v; sq += v*v; }
        float mu = sum / C;
        float var = sq / C - mu*mu;
        smu[p] = mu; srv[p] = rsqrtf(var + 1e-5f);
    }
    __syncthreads();
    for (int e = threadIdx.x; e < C*32; e += 256) {
        int p = e / C, c = e % C;
        float v = s[c*33 + p];
        int gi = (pix0 + p)*C + c;
        g_xt[gi] = v;
        g_xn[gi] = (v - smu[p]) * srv[p] * w[c] + b[c];
    }
}

// ================= K2: fused window attention ==================
#define SQ 196   // token-major row stride for Q/K/V/O (mult of 4)
#define XT 68    // k-major stride for XsT / As / Bs
__global__ __launch_bounds__(256,1) void k_attn(
    const float* __restrict__ qkv_w, const float* __restrict__ rpb,
    const float* __restrict__ proj_w, const float* __restrict__ proj_b)
{
    extern __shared__ float sm[];
    float* XsT = sm;                 // [192][68] (k-major input); later O [64][196]
    float* Qs  = sm + 192*XT;        // [64][196]
    float* Ks  = Qs + 64*SQ;
    float* Vs  = Ks + 64*SQ;
    float* As  = Vs + 64*SQ;         // [64][68] attn scores; also weight tile Bs
    float* Bs  = As;
    __shared__ int lab[64];
    __shared__ int gbase[64];

    int tid = threadIdx.x;
    int bb = blockIdx.x >> 10;
    int wy = (blockIdx.x >> 5) & 31;
    int wx = blockIdx.x & 31;

    if (tid < 64) {
        int i1 = tid >> 3, j1 = tid & 7;
        int sr = wy*8 + i1, sc = wx*8 + j1;
        lab[tid] = ((sr >= HH-WS) + (sr >= HH-SS))*3 + ((sc >= WW-WS) + (sc >= WW-SS));
        int r = (sr + SS) & (HH-1), c2 = (sc + SS) & (WW-1);
        gbase[tid] = ((bb*HH + r)*WW + c2)*C;
    }
    __syncthreads();
    for (int e = tid; e < 64*C; e += 256) {
        int n = e / C, c = e % C;
        XsT[c*XT + n] = g_xn[gbase[n] + c];
    }
    __syncthreads();

    int tx = tid & 15, ty = tid >> 4;
    const float qscale = 0.20412414523193154f;  // 24^-0.5

    // ---- QKV GEMM: 64 tok x 576 out, K=192 ----
    for (int dt = 0; dt < 9; dt++) {
        float acc[4][4] = {};
        for (int k0 = 0; k0 < C; k0 += 32) {
            __syncthreads();
            for (int e = tid; e < 2048; e += 256) {
                int o = e >> 5, kk = e & 31;
                Bs[kk*XT + o] = qkv_w[(dt*64 + o)*C + k0 + kk];
            }
            __syncthreads();
            #pragma unroll
            for (int kk = 0; kk < 32; kk++) {
                float4 xv = *(const float4*)&XsT[(k0+kk)*XT + ty*4];
                float4 wv = *(const float4*)&Bs[kk*XT + tx*4];
                float xa[4] = {xv.x,xv.y,xv.z,xv.w};
                float wa[4] = {wv.x,wv.y,wv.z,wv.w};
                #pragma unroll
                for (int i=0;i<4;i++)
                    #pragma unroll
                    for (int j=0;j<4;j++)
                        acc[i][j] += xa[i]*wa[j];
            }
        }
        __syncthreads();
        #pragma unroll
        for (int i=0;i<4;i++) {
            int n = ty*4 + i;
            #pragma unroll
            for (int j=0;j<4;j++) {
                int d = dt*64 + tx*4 + j;
                float v = acc[i][j];
                if (d < C)        Qs[n*SQ + d] = v * qscale;
                else if (d < 2*C) Ks[n*SQ + (d - C)] = v;
                else              Vs[n*SQ + (d - 2*C)] = v;
            }
        }
    }
    __syncthreads();

    // ---- per-head attention ----
    for (int h = 0; h < NH; h++) {
        int off = h*HD;
        {   // QK^T + bias + mask : thread computes 4n x 4m
            int m0 = tx*4, n0 = ty*4;
            float a[4][4] = {};
            #pragma unroll
            for (int d4 = 0; d4 < 6; d4++) {
                float4 q[4], kv[4];
                #pragma unroll
                for (int i=0;i<4;i++) q[i] = *(const float4*)&Qs[(n0+i)*SQ + off + d4*4];
                #pragma unroll
                for (int j=0;j<4;j++) kv[j] = *(const float4*)&Ks[(m0+j)*SQ + off + d4*4];
                #pragma unroll
                for (int i=0;i<4;i++)
                  #pragma unroll
                  for (int j=0;j<4;j++)
                    a[i][j] += q[i].x*kv[j].x + q[i].y*kv[j].y + q[i].z*kv[j].z + q[i].w*kv[j].w;
            }
            #pragma unroll
            for (int i=0;i<4;i++) {
                int n = n0+i; int i1 = n>>3, j1 = n&7;
                #pragma unroll
                for (int j=0;j<4;j++) {
                    int m = m0+j; int i2 = m>>3, j2 = m&7;
                    float v = a[i][j] + rpb[((i1-i2+7)*15 + (j1-j2+7))*NH + h];
                    if (lab[n] != lab[m]) v -= 100.f;
                    As[n*XT + m] = v;
                }
            }
        }
        __syncthreads();
        if (tid < 64) {   // softmax per row
            float* row = &As[tid*XT];
            float mx = row[0];
            #pragma unroll
            for (int m=1;m<64;m++) mx = fmaxf(mx, row[m]);
            float s2 = 0.f;
            for (int m=0;m<64;m++) { float e2 = expf(row[m]-mx); row[m]=e2; s2+=e2; }
            float inv = 1.f/s2;
            for (int m=0;m<64;m++) row[m] *= inv;
        }
        __syncthreads();
        // AV -> O (stored in XsT region, token-major stride SQ)
        for (int e = tid; e < 64*6; e += 256) {
            int n = e / 6, d4 = e % 6;
            float4 acc = make_float4(0.f,0.f,0.f,0.f);
            const float* arow = &As[n*XT];
            #pragma unroll 8
            for (int m=0;m<64;m++) {
                float a = arow[m];
                float4 v = *(const float4*)&Vs[m*SQ + off + d4*4];
                acc.x += a*v.x; acc.y += a*v.y; acc.z += a*v.z; acc.w += a*v.w;
            }
            *(float4*)&XsT[n*SQ + off + d4*4] = acc;
        }
        __syncthreads();
    }

    // ---- proj + residual -> g_x2 ----
    float* O = XsT;
    for (int dt = 0; dt < 3; dt++) {
        float acc[4][4] = {};
        for (int k0 = 0; k0 < C; k0 += 32) {
            __syncthreads();
            for (int e = tid; e < 2048; e += 256) {
                int o = e >> 5, kk = e & 31;
                Bs[o*36 + kk] = proj_w[(dt*64 + o)*C + k0 + kk];
            }
            __syncthreads();
            #pragma unroll
            for (int k4 = 0; k4 < 8; k4++) {
                float4 ov[4], wv[4];
                #pragma unroll
                for (int i=0;i<4;i++) ov[i] = *(const float4*)&O[(ty*4+i)*SQ + k0 + k4*4];
                #pragma unroll
                for (int j=0;j<4;j++) wv[j] = *(const float4*)&Bs[(tx*4+j)*36 + k4*4];
                #pragma unroll
                for (int i=0;i<4;i++)
                  #pragma unroll
                  for (int j=0;j<4;j++)
                    acc[i][j] += ov[i].x*wv[j].x + ov[i].y*wv[j].y + ov[i].z*wv[j].z + ov[i].w*wv[j].w;
            }
        }
        #pragma unroll
        for (int i=0;i<4;i++) {
            int n = ty*4 + i;
            #pragma unroll
            for (int j=0;j<4;j++) {
                int c = dt*64 + tx*4 + j;
                int gi = gbase[n] + c;
                g_x2[gi] = g_xt[gi] + acc[i][j] + proj_b[c];
            }
        }
    }
}

// ================= K3: LN2 ==================
__global__ __launch_bounds__(256) void k_ln2(const float* __restrict__ w,
                                             const float* __restrict__ b) {
    int pix = blockIdx.x*8 + (threadIdx.x >> 5);
    int lane = threadIdx.x & 31;
    const float* row = g_x2 + (size_t)pix*C;
    float v[6];
    float sum = 0.f, sq = 0.f;
    #pragma unroll
    for (int i=0;i<6;i++) { v[i] = row[lane + 32*i]; sum += v[i]; sq += v[i]*v[i]; }
    #pragma unroll
    for (int o=16;o;o>>=1) { sum += __shfl_xor_sync(0xffffffffu,sum,o);
                             sq  += __shfl_xor_sync(0xffffffffu,sq ,o); }
    float mu = sum / C;
    float rv = rsqrtf(sq / C - mu*mu + 1e-5f);
    float* outp = g_yn + (size_t)pix*C;
    #pragma unroll
    for (int i=0;i<6;i++) { int c = lane + 32*i; outp[c] = (v[i]-mu)*rv*w[c] + b[c]; }
}

// ================= K4: pin GEMM (131072 x 1020 x 192) tf32 tensor ==================
// CTA tile 128 pix x 128 out, 8 warps (2 m-groups x 4 n-groups), warp tile 64x32.
__global__ __launch_bounds__(256) void k_pin_t(const float* __restrict__ pw) {
    __shared__ float As[128*36];   // [pix][k] pad 36
    __shared__ float Bs[128*36];   // [o][k]   pad 36
    int pt = blockIdx.y * 128;
    int ot = blockIdx.x * 128;
    int tid = threadIdx.x;
    int warp = tid >> 5, lane = tid & 31;
    int m0 = (warp >> 2) * 64;
    int n0 = (warp & 3) * 32;
    int lr = lane >> 2, lc = lane & 3;

    float acc[4][4][4] = {};
    for (int k0 = 0; k0 < C; k0 += 32) {
        __syncthreads();
        #pragma unroll
        for (int e = tid; e < 4096; e += 256) {
            int r = e >> 5, kk = e & 31;
            As[r*36 + kk] = to_tf32(g_yn[(size_t)(pt + r)*C + k0 + kk]);
        }
        #pragma unroll
        for (int e = tid; e < 4096; e += 256) {
            int o = e >> 5, kk = e & 31;
            int og = ot + o;
            Bs[o*36 + kk] = (og < HID2) ? to_tf32(pw[og*C + k0 + kk]) : 0.f;
        }
        __syncthreads();
        #pragma unroll
        for (int q = 0; q < 4; q++) {
            int kq = q*8 + lc;
            float af[4][4], bf[4][2];
            #pragma unroll
            for (int mt = 0; mt < 4; mt++) {
                int row = m0 + mt*16 + lr;
                af[mt][0] = As[row*36 + kq];
                af[mt][1] = As[(row+8)*36 + kq];
                af[mt][2] = As[row*36 + kq + 4];
                af[mt][3] = As[(row+8)*36 + kq + 4];
            }
            #pragma unroll
            for (int nt = 0; nt < 4; nt++) {
                int col = n0 + nt*8 + lr;
                bf[nt][0] = Bs[col*36 + kq];
                bf[nt][1] = Bs[col*36 + kq + 4];
            }
            #pragma unroll
            for (int mt = 0; mt < 4; mt++)
                #pragma unroll
                for (int nt = 0; nt < 4; nt++)
                    mma_tf32(acc[mt][nt][0], acc[mt][nt][1], acc[mt][nt][2], acc[mt][nt][3],
                             af[mt][0], af[mt][1], af[mt][2], af[mt][3],
                             bf[nt][0], bf[nt][1]);
        }
    }
    // epilogue: direct float2 stores (quad lanes fill one 32B sector)
    #pragma unroll
    for (int mt = 0; mt < 4; mt++) {
        int row = pt + m0 + mt*16 + lr;
        #pragma unroll
        for (int nt = 0; nt < 4; nt++) {
            int col = ot + n0 + nt*8 + 2*lc;
            if (col < HID2) {
                *(float2*)&g_y[(size_t)row*HID2 + col] = make_float2(acc[mt][nt][0], acc[mt][nt][1]);
                *(float2*)&g_y[(size_t)(row+8)*HID2 + col] = make_float2(acc[mt][nt][2], acc[mt][nt][3]);
            }
        }
    }
}

// ================= K5: depthwise 3x3 + gated GELU ==================
__global__ __launch_bounds__(256) void k_dw(const float* __restrict__ dw) {
    int bx = blockIdx.x;               // B * H * (W/4) = 32768
    int c = blockIdx.y * 256 + threadIdx.x;
    if (c >= HID) return;
    int xseg = (bx & 63) * 4;
    int r = (bx >> 6) & 255;
    int bb = bx >> 14;
    float ya[3][6], yb[3][6];
    #pragma unroll
    for (int dy = 0; dy < 3; dy++) {
        int rowi = r + dy - 1;
        bool rok = (unsigned)rowi < 256u;
        #pragma unroll
        for (int dx = 0; dx < 6; dx++) {
            int col = xseg + dx - 1;
            bool ok = rok && ((unsigned)col < 256u);
            size_t base = ((size_t)(bb*HH + rowi)*WW + col)*HID2;
            ya[dy][dx] = ok ? g_y[base + c] : 0.f;
            yb[dy][dx] = ok ? g_y[base + c + HID] : 0.f;
        }
    }
    float wa[9], wb[9];
    #pragma unroll
    for (int t = 0; t < 9; t++) { wa[t] = dw[c*9 + t]; wb[t] = dw[(c + HID)*9 + t]; }
    #pragma unroll
    for (int o = 0; o < 4; o++) {
        float a = 0.f, g2 = 0.f;
        #pragma unroll
        for (int ky = 0; ky < 3; ky++)
          #pragma unroll
          for (int kx = 0; kx < 3; kx++) {
            a  += wa[ky*3+kx] * ya[ky][o+kx];
            g2 += wb[ky*3+kx] * yb[ky][o+kx];
          }
        float ge = 0.5f * a * (1.f + erff(a * 0.70710678118654752f));
        g_g[((size_t)(bb*HH + r)*WW + xseg + o)*HID + c] = ge * g2;
    }
}

// ================= K6: pout GEMM (131072 x 192 x 510) tf32 + residual -> NCHW ==================
// CTA tile 128 pix x 64 c, 8 warps (4 m x 2 n), warp tile 32x32.
#define SPP 132
__global__ __launch_bounds__(256) void k_pout_t(const float* __restrict__ pw,
                                                float* __restrict__ outp) {
    __shared__ float smbuf[64*SPP];   // Cs [c][pix]; first part doubles as As/Bs
    float* As = smbuf;                // [128][36]
    float* Bs = smbuf + 128*36;       // [64][36]  (total 6912 floats < 8448)
    float* Cs = smbuf;

    int pt = blockIdx.y * 128;
    int ct = blockIdx.x * 64;
    int tid = threadIdx.x;
    int warp = tid >> 5, lane = tid & 31;
    int m0 = (warp & 3) * 32;
    int n0 = (warp >> 2) * 32;
    int lr = lane >> 2, lc = lane & 3;

    float acc[2][4][4] = {};
    for (int k0 = 0; k0 < HID; k0 += 32) {
        __syncthreads();
        int kmax = HID - k0;
        #pragma unroll
        for (int e = tid; e < 4096; e += 256) {
            int r = e >> 5, kk = e & 31;
            As[r*36 + kk] = (kk < kmax) ? to_tf32(g_g[(size_t)(pt + r)*HID + k0 + kk]) : 0.f;
        }
        #pragma unroll
        for (int e = tid; e < 2048; e += 256) {
            int o = e >> 5, kk = e & 31;
            Bs[o*36 + kk] = (kk < kmax) ? to_tf32(pw[(ct + o)*HID + k0 + kk]) : 0.f;
        }
        __syncthreads();
        #pragma unroll
        for (int q = 0; q < 4; q++) {
            int kq = q*8 + lc;
            float af[2][4], bf[4][2];
            #pragma unroll
            for (int mt = 0; mt < 2; mt++) {
                int row = m0 + mt*16 + lr;
                af[mt][0] = As[row*36 + kq];
                af[mt][1] = As[(row+8)*36 + kq];
                af[mt][2] = As[row*36 + kq + 4];
                af[mt][3] = As[(row+8)*36 + kq + 4];
            }
            #pragma unroll
            for (int nt = 0; nt < 4; nt++) {
                int col = n0 + nt*8 + lr;
                bf[nt][0] = Bs[col*36 + kq];
                bf[nt][1] = Bs[col*36 + kq + 4];
            }
            #pragma unroll
            for (int mt = 0; mt < 2; mt++)
                #pragma unroll
                for (int nt = 0; nt < 4; nt++)
                    mma_tf32(acc[mt][nt][0], acc[mt][nt][1], acc[mt][nt][2], acc[mt][nt][3],
                             af[mt][0], af[mt][1], af[mt][2], af[mt][3],
                             bf[nt][0], bf[nt][1]);
        }
    }
    __syncthreads();
    // store frags transposed: Cs[c][pix]
    #pragma unroll
    for (int mt = 0; mt < 2; mt++) {
        int row = m0 + mt*16 + lr;
        #pragma unroll
        for (int nt = 0; nt < 4; nt++) {
            int col = n0 + nt*8 + 2*lc;
            Cs[col*SPP + row] = acc[mt][nt][0];
            Cs[(col+1)*SPP + row] = acc[mt][nt][1];
            Cs[col*SPP + row + 8] = acc[mt][nt][2];
            Cs[(col+1)*SPP + row + 8] = acc[mt][nt][3];
        }
    }
    __syncthreads();
    // residual add from g_x2 [pix][c]
    #pragma unroll
    for (int e = tid; e < 2048; e += 256) {
        int p = e >> 4, c4 = e & 15;
        float4 v = *(const float4*)&g_x2[(size_t)(pt + p)*C + ct + c4*4];
        Cs[(c4*4+0)*SPP + p] += v.x;
        Cs[(c4*4+1)*SPP + p] += v.y;
        Cs[(c4*4+2)*SPP + p] += v.z;
        Cs[(c4*4+3)*SPP + p] += v.w;
    }
    __syncthreads();
    int bb = pt >> 16;
    int hw0 = pt & 65535;
    #pragma unroll
    for (int e = tid; e < 2048; e += 256) {
        int c = e >> 5, p4 = e & 31;
        float4 v = *(const float4*)&Cs[c*SPP + p4*4];
        *(float4*)&outp[((size_t)(bb*C + ct + c))*HW + hw0 + p4*4] = v;
    }
}

// ================= launch ==================
extern "C" void kernel_launch(void* const* d_in, const int* in_sizes, int n_in,
                              void* d_out, int out_size) {
    const float* x      = (const float*)d_in[0];
    const float* n1w    = (const float*)d_in[1];
    const float* n1b    = (const float*)d_in[2];
    const float* qkv_w  = (const float*)d_in[3];
    const float* rpb    = (const float*)d_in[4];
    const float* proj_w = (const float*)d_in[5];
    const float* proj_b = (const float*)d_in[6];
    const float* n2w    = (const float*)d_in[7];
    const float* n2b    = (const float*)d_in[8];
    const float* pin_w  = (const float*)d_in[9];
    const float* dw_w   = (const float*)d_in[10];
    const float* pout_w = (const float*)d_in[11];
    float* outp = (float*)d_out;

    const int attn_smem = (192*XT + 3*64*SQ + 64*XT) * 4;   // 220160 B
    cudaFuncSetAttribute(k_attn, cudaFuncAttributeMaxDynamicSharedMemorySize, attn_smem);

    k_ln1  <<<NPIX/32, 256>>>(x, n1w, n1b);
    k_attn <<<2048, 256, attn_smem>>>(qkv_w, rpb, proj_w, proj_b);
    k_ln2  <<<NPIX/8, 256>>>(n2w, n2b);
    k_pin_t<<<dim3(8, NPIX/128), 256>>>(pin_w);
    k_dw   <<<dim3(BATCH*HH*(WW/4), 2), 256>>>(dw_w);
    k_pout_t<<<dim3(3, NPIX/128), 256>>>(pout_w, outp);
}

// round 6
// speedup vs baseline: 1.5072x; 1.3288x over previous
#include <cuda_runtime.h>
#include <cuda_bf16.h>
#include <stdint.h>
#include <math.h>

typedef unsigned int u32;

#define BATCH 2
#define C 192
#define HH 256
#define WW 256
#define HW (HH*WW)
#define NPIX (BATCH*HW)
#define NH 8
#define HD 24
#define WS 8
#define SS 4
#define HID 510
#define HID2 1020

// ---- scratch ----
__device__ float g_xn[NPIX*C];
__device__ float g_xt[NPIX*C];
__device__ float g_x2[NPIX*C];
__device__ __nv_bfloat16 g_ynb[(size_t)NPIX*C];
__device__ __nv_bfloat16 g_y[(size_t)NPIX*HID2];
__device__ __nv_bfloat16 g_gg[(size_t)NPIX*512];
__device__ __nv_bfloat16 g_pinb[HID2*C];
__device__ __nv_bfloat16 g_poutb[C*512];

__device__ __forceinline__ u32 sptr(const void* p) {
    return (u32)__cvta_generic_to_shared(p);
}
__device__ __forceinline__ void cpa16(u32 dst, const void* src, bool full) {
    int sz = full ? 16 : 0;
    asm volatile("cp.async.cg.shared.global [%0], [%1], 16, %2;" :: "r"(dst), "l"(src), "r"(sz));
}
__device__ __forceinline__ void ldsm4(u32& r0, u32& r1, u32& r2, u32& r3, u32 a) {
    asm volatile("ldmatrix.sync.aligned.m8n8.x4.shared.b16 {%0,%1,%2,%3}, [%4];"
        : "=r"(r0), "=r"(r1), "=r"(r2), "=r"(r3) : "r"(a));
}
__device__ __forceinline__ void mma_bf16(float& c0, float& c1, float& c2, float& c3,
    u32 a0, u32 a1, u32 a2, u32 a3, u32 b0, u32 b1) {
    asm volatile("mma.sync.aligned.m16n8k16.row.col.f32.bf16.bf16.f32 "
        "{%0,%1,%2,%3}, {%4,%5,%6,%7}, {%8,%9}, {%0,%1,%2,%3};"
        : "+f"(c0), "+f"(c1), "+f"(c2), "+f"(c3)
        : "r"(a0), "r"(a1), "r"(a2), "r"(a3), "r"(b0), "r"(b1));
}

// ================= weight converts ==================
__global__ void k_cvt_pin(const float* __restrict__ src) {
    int i = blockIdx.x*256 + threadIdx.x;
    if (i < HID2*C) {
        g_pinb[i] = __float2bfloat16(src[i]);
    }
}
__global__ void k_cvt_pout(const float* __restrict__ src) {
    int i = blockIdx.x*256 + threadIdx.x;
    if (i < C*512) {
        int o = i >> 9;
        int k = i & 511;
        g_poutb[i] = __float2bfloat16(k < HID ? src[o*HID + k] : 0.f);
    }
}

// ================= K1: LN1 + transpose ==================
__global__ __launch_bounds__(256) void k_ln1(const float* __restrict__ x,
        const float* __restrict__ w, const float* __restrict__ b) {
    __shared__ float s[C*33];
    __shared__ float smu[32];
    __shared__ float srv[32];
    int pix0 = blockIdx.x * 32;
    int bb = pix0 / HW;
    int hw0 = pix0 % HW;
    for (int e = threadIdx.x; e < C*32; e += 256) {
        int c = e >> 5;
        int p = e & 31;
        s[c*33 + p] = x[(size_t)(bb*C + c)*HW + hw0 + p];
    }
    __syncthreads();
    if (threadIdx.x < 32) {
        int p = threadIdx.x;
        float sum = 0.f;
        float sq = 0.f;
        for (int c = 0; c < C; c++) {
            float v = s[c*33+p];
            sum += v;
            sq += v*v;
        }
        float mu = sum / C;
        float var = sq / C - mu*mu;
        smu[p] = mu;
        srv[p] = rsqrtf(var + 1e-5f);
    }
    __syncthreads();
    for (int e = threadIdx.x; e < C*32; e += 256) {
        int p = e / C;
        int c = e % C;
        float v = s[c*33 + p];
        int gi = (pix0 + p)*C + c;
        g_xt[gi] = v;
        g_xn[gi] = (v - smu[p]) * srv[p] * w[c] + b[c];
    }
}

// ================= K2: fused window attention (fp32) ==================
#define SQ 196
#define XT 68
__global__ __launch_bounds__(256,1) void k_attn(
    const float* __restrict__ qkv_w, const float* __restrict__ rpb,
    const float* __restrict__ proj_w, const float* __restrict__ proj_b)
{
    extern __shared__ float sm[];
    float* XsT = sm;
    float* Qs  = sm + 192*XT;
    float* Ks  = Qs + 64*SQ;
    float* Vs  = Ks + 64*SQ;
    float* As  = Vs + 64*SQ;
    float* Bs  = As;
    __shared__ int lab[64];
    __shared__ int gbase[64];

    int tid = threadIdx.x;
    int bb = blockIdx.x >> 10;
    int wy = (blockIdx.x >> 5) & 31;
    int wx = blockIdx.x & 31;

    if (tid < 64) {
        int i1 = tid >> 3;
        int j1 = tid & 7;
        int sr = wy*8 + i1;
        int sc = wx*8 + j1;
        lab[tid] = ((sr >= HH-WS) + (sr >= HH-SS))*3 + ((sc >= WW-WS) + (sc >= WW-SS));
        int r = (sr + SS) & (HH-1);
        int c2 = (sc + SS) & (WW-1);
        gbase[tid] = ((bb*HH + r)*WW + c2)*C;
    }
    __syncthreads();
    for (int e = tid; e < 64*C; e += 256) {
        int n = e / C;
        int c = e % C;
        XsT[c*XT + n] = g_xn[gbase[n] + c];
    }
    __syncthreads();

    int tx = tid & 15;
    int ty = tid >> 4;
    const float qscale = 0.20412414523193154f;

    for (int dt = 0; dt < 9; dt++) {
        float acc[4][4] = {};
        for (int k0 = 0; k0 < C; k0 += 32) {
            __syncthreads();
            for (int e = tid; e < 2048; e += 256) {
                int o = e >> 5;
                int kk = e & 31;
                Bs[kk*XT + o] = qkv_w[(dt*64 + o)*C + k0 + kk];
            }
            __syncthreads();
            #pragma unroll
            for (int kk = 0; kk < 32; kk++) {
                float4 xv = *(const float4*)&XsT[(k0+kk)*XT + ty*4];
                float4 wv = *(const float4*)&Bs[kk*XT + tx*4];
                float xa[4] = {xv.x,xv.y,xv.z,xv.w};
                float wa[4] = {wv.x,wv.y,wv.z,wv.w};
                #pragma unroll
                for (int i = 0; i < 4; i++) {
                    #pragma unroll
                    for (int j = 0; j < 4; j++) {
                        acc[i][j] += xa[i]*wa[j];
                    }
                }
            }
        }
        __syncthreads();
        #pragma unroll
        for (int i = 0; i < 4; i++) {
            int n = ty*4 + i;
            #pragma unroll
            for (int j = 0; j < 4; j++) {
                int d = dt*64 + tx*4 + j;
                float v = acc[i][j];
                if (d < C) {
                    Qs[n*SQ + d] = v * qscale;
                } else if (d < 2*C) {
                    Ks[n*SQ + (d - C)] = v;
                } else {
                    Vs[n*SQ + (d - 2*C)] = v;
                }
            }
        }
    }
    __syncthreads();

    for (int h = 0; h < NH; h++) {
        int off = h*HD;
        int m0 = tx*4;
        int n0 = ty*4;
        float a[4][4] = {};
        #pragma unroll
        for (int d4 = 0; d4 < 6; d4++) {
            float4 q[4];
            float4 kv[4];
            #pragma unroll
            for (int i = 0; i < 4; i++) {
                q[i] = *(const float4*)&Qs[(n0+i)*SQ + off + d4*4];
            }
            #pragma unroll
            for (int j = 0; j < 4; j++) {
                kv[j] = *(const float4*)&Ks[(m0+j)*SQ + off + d4*4];
            }
            #pragma unroll
            for (int i = 0; i < 4; i++) {
                #pragma unroll
                for (int j = 0; j < 4; j++) {
                    a[i][j] += q[i].x*kv[j].x + q[i].y*kv[j].y + q[i].z*kv[j].z + q[i].w*kv[j].w;
                }
            }
        }
        #pragma unroll
        for (int i = 0; i < 4; i++) {
            int n = n0+i;
            int i1 = n>>3;
            int j1 = n&7;
            #pragma unroll
            for (int j = 0; j < 4; j++) {
                int m = m0+j;
                int i2 = m>>3;
                int j2 = m&7;
                float v = a[i][j] + rpb[((i1-i2+7)*15 + (j1-j2+7))*NH + h];
                if (lab[n] != lab[m]) {
                    v -= 100.f;
                }
                As[n*XT + m] = v;
            }
        }
        __syncthreads();
        if (tid < 64) {
            float* row = &As[tid*XT];
            float mx = row[0];
            #pragma unroll
            for (int m = 1; m < 64; m++) {
                mx = fmaxf(mx, row[m]);
            }
            float s2 = 0.f;
            for (int m = 0; m < 64; m++) {
                float e2 = expf(row[m]-mx);
                row[m] = e2;
                s2 += e2;
            }
            float inv = 1.f/s2;
            for (int m = 0; m < 64; m++) {
                row[m] *= inv;
            }
        }
        __syncthreads();
        for (int e = tid; e < 64*6; e += 256) {
            int n = e / 6;
            int d4 = e % 6;
            float4 acc2 = make_float4(0.f,0.f,0.f,0.f);
            const float* arow = &As[n*XT];
            #pragma unroll 8
            for (int m = 0; m < 64; m++) {
                float av = arow[m];
                float4 v = *(const float4*)&Vs[m*SQ + off + d4*4];
                acc2.x += av*v.x;
                acc2.y += av*v.y;
                acc2.z += av*v.z;
                acc2.w += av*v.w;
            }
            *(float4*)&XsT[n*SQ + off + d4*4] = acc2;
        }
        __syncthreads();
    }

    float* O = XsT;
    for (int dt = 0; dt < 3; dt++) {
        float acc[4][4] = {};
        for (int k0 = 0; k0 < C; k0 += 32) {
            __syncthreads();
            for (int e = tid; e < 2048; e += 256) {
                int o = e >> 5;
                int kk = e & 31;
                Bs[o*36 + kk] = proj_w[(dt*64 + o)*C + k0 + kk];
            }
            __syncthreads();
            #pragma unroll
            for (int k4 = 0; k4 < 8; k4++) {
                float4 ov[4];
                float4 wv[4];
                #pragma unroll
                for (int i = 0; i < 4; i++) {
                    ov[i] = *(const float4*)&O[(ty*4+i)*SQ + k0 + k4*4];
                }
                #pragma unroll
                for (int j = 0; j < 4; j++) {
                    wv[j] = *(const float4*)&Bs[(tx*4+j)*36 + k4*4];
                }
                #pragma unroll
                for (int i = 0; i < 4; i++) {
                    #pragma unroll
                    for (int j = 0; j < 4; j++) {
                        acc[i][j] += ov[i].x*wv[j].x + ov[i].y*wv[j].y + ov[i].z*wv[j].z + ov[i].w*wv[j].w;
                    }
                }
            }
        }
        #pragma unroll
        for (int i = 0; i < 4; i++) {
            int n = ty*4 + i;
            #pragma unroll
            for (int j = 0; j < 4; j++) {
                int c = dt*64 + tx*4 + j;
                int gi = gbase[n] + c;
                g_x2[gi] = g_xt[gi] + acc[i][j] + proj_b[c];
            }
        }
    }
}

// ================= K3: LN2 -> bf16 ==================
__global__ __launch_bounds__(256) void k_ln2(const float* __restrict__ w,
                                             const float* __restrict__ b) {
    int pix = blockIdx.x*8 + (threadIdx.x >> 5);
    int lane = threadIdx.x & 31;
    const float* row = g_x2 + (size_t)pix*C;
    float v[6];
    float sum = 0.f;
    float sq = 0.f;
    #pragma unroll
    for (int i = 0; i < 6; i++) {
        v[i] = row[lane + 32*i];
        sum += v[i];
        sq += v[i]*v[i];
    }
    #pragma unroll
    for (int o = 16; o; o >>= 1) {
        sum += __shfl_xor_sync(0xffffffffu, sum, o);
        sq  += __shfl_xor_sync(0xffffffffu, sq, o);
    }
    float mu = sum / C;
    float rv = rsqrtf(sq / C - mu*mu + 1e-5f);
    __nv_bfloat16* outp = g_ynb + (size_t)pix*C;
    #pragma unroll
    for (int i = 0; i < 6; i++) {
        int c = lane + 32*i;
        outp[c] = __float2bfloat16((v[i]-mu)*rv*w[c] + b[c]);
    }
}

// ================= tile loaders for bf16 GEMMs ==================
__device__ __forceinline__ void pin_load(__nv_bfloat16* Adst, __nv_bfloat16* Bdst,
                                         int pt, int ot, int k0, int tid) {
    #pragma unroll
    for (int i = 0; i < 2; i++) {
        int e = tid + i*256;
        int row = e >> 2;
        int seg = e & 3;
        cpa16(sptr(Adst + row*40 + seg*8), g_ynb + (size_t)(pt + row)*C + k0 + seg*8, true);
        int og = ot + row;
        bool ok = og < HID2;
        cpa16(sptr(Bdst + row*40 + seg*8), g_pinb + (size_t)(ok ? og : 0)*C + k0 + seg*8, ok);
    }
    asm volatile("cp.async.commit_group;" ::: "memory");
}

__device__ __forceinline__ void pout_load(__nv_bfloat16* Adst, __nv_bfloat16* Bdst,
                                          int pt, int ct, int k0, int tid) {
    #pragma unroll
    for (int i = 0; i < 2; i++) {
        int e = tid + i*256;
        int row = e >> 2;
        int seg = e & 3;
        cpa16(sptr(Adst + row*40 + seg*8), g_gg + (size_t)(pt + row)*512 + k0 + seg*8, true);
    }
    int row = tid >> 2;
    int seg = tid & 3;
    cpa16(sptr(Bdst + row*40 + seg*8), g_poutb + (size_t)(ct + row)*512 + k0 + seg*8, true);
    asm volatile("cp.async.commit_group;" ::: "memory");
}

// ================= K4: pin GEMM bf16 (131072 x 1020 x 192) ==================
__global__ __launch_bounds__(256,2) void k_pin_b() {
    __shared__ __align__(16) __nv_bfloat16 As[2][5120];
    __shared__ __align__(16) __nv_bfloat16 Bs[2][5120];
    int pt = blockIdx.y*128;
    int ot = blockIdx.x*128;
    int tid = threadIdx.x;
    int lane = tid & 31;
    int warp = tid >> 5;
    int m0 = (warp >> 2)*64;
    int n0 = (warp & 3)*32;
    float acc[4][4][4] = {};

    pin_load(As[0], Bs[0], pt, ot, 0, tid);

    for (int ch = 0; ch < 6; ch++) {
        asm volatile("cp.async.wait_group 0;" ::: "memory");
        __syncthreads();
        if (ch < 5) {
            pin_load(As[(ch+1)&1], Bs[(ch+1)&1], pt, ot, (ch+1)*32, tid);
        }
        u32 ab = sptr(As[ch & 1]);
        u32 bbs = sptr(Bs[ch & 1]);
        #pragma unroll
        for (int ks = 0; ks < 2; ks++) {
            u32 av[4][4];
            u32 bv[4][2];
            #pragma unroll
            for (int mt = 0; mt < 4; mt++) {
                int row = m0 + mt*16 + (lane & 15);
                u32 ad = ab + (row*40 + ((lane >> 4) & 1)*8 + ks*16)*2;
                ldsm4(av[mt][0], av[mt][1], av[mt][2], av[mt][3], ad);
            }
            #pragma unroll
            for (int n2 = 0; n2 < 2; n2++) {
                int row = n0 + n2*16 + (lane & 7) + ((lane >> 4) & 1)*8;
                u32 ad = bbs + (row*40 + ((lane >> 3) & 1)*8 + ks*16)*2;
                u32 r0;
                u32 r1;
                u32 r2;
                u32 r3;
                ldsm4(r0, r1, r2, r3, ad);
                bv[n2*2+0][0] = r0;
                bv[n2*2+0][1] = r1;
                bv[n2*2+1][0] = r2;
                bv[n2*2+1][1] = r3;
            }
            #pragma unroll
            for (int mt = 0; mt < 4; mt++) {
                #pragma unroll
                for (int nt = 0; nt < 4; nt++) {
                    mma_bf16(acc[mt][nt][0], acc[mt][nt][1], acc[mt][nt][2], acc[mt][nt][3],
                             av[mt][0], av[mt][1], av[mt][2], av[mt][3], bv[nt][0], bv[nt][1]);
                }
            }
        }
    }

    int lr = lane >> 2;
    int lc = lane & 3;
    #pragma unroll
    for (int mt = 0; mt < 4; mt++) {
        int row = pt + m0 + mt*16 + lr;
        #pragma unroll
        for (int nt = 0; nt < 4; nt++) {
            int col = ot + n0 + nt*8 + 2*lc;
            if (col < HID2) {
                __nv_bfloat162 v0;
                v0.x = __float2bfloat16(acc[mt][nt][0]);
                v0.y = __float2bfloat16(acc[mt][nt][1]);
                *(__nv_bfloat162*)&g_y[(size_t)row*HID2 + col] = v0;
                __nv_bfloat162 v1;
                v1.x = __float2bfloat16(acc[mt][nt][2]);
                v1.y = __float2bfloat16(acc[mt][nt][3]);
                *(__nv_bfloat162*)&g_y[(size_t)(row+8)*HID2 + col] = v1;
            }
        }
    }
}

// ================= K5: depthwise 3x3 + gated GELU (bf16 in/out) ==================
__global__ __launch_bounds__(256) void k_dw(const float* __restrict__ dw) {
    int bx = blockIdx.x;
    int c = blockIdx.y * 256 + threadIdx.x;
    int xseg = (bx & 63) * 4;
    int r = (bx >> 6) & 255;
    int bb = bx >> 14;
    if (blockIdx.y == 0 && threadIdx.x < 2) {
        #pragma unroll
        for (int o = 0; o < 4; o++) {
            g_gg[((size_t)(bb*HH + r)*WW + xseg + o)*512 + HID + threadIdx.x] = __float2bfloat16(0.f);
        }
    }
    if (c >= HID) {
        return;
    }
    float ya[3][6];
    float yb[3][6];
    #pragma unroll
    for (int dy = 0; dy < 3; dy++) {
        int rowi = r + dy - 1;
        bool rok = (unsigned)rowi < 256u;
        #pragma unroll
        for (int dx = 0; dx < 6; dx++) {
            int col = xseg + dx - 1;
            bool ok = rok && ((unsigned)col < 256u);
            size_t base = ((size_t)(bb*HH + rowi)*WW + col)*HID2;
            ya[dy][dx] = ok ? __bfloat162float(g_y[base + c]) : 0.f;
            yb[dy][dx] = ok ? __bfloat162float(g_y[base + c + HID]) : 0.f;
        }
    }
    float wa[9];
    float wb[9];
    #pragma unroll
    for (int t = 0; t < 9; t++) {
        wa[t] = dw[c*9 + t];
        wb[t] = dw[(c + HID)*9 + t];
    }
    #pragma unroll
    for (int o = 0; o < 4; o++) {
        float a = 0.f;
        float g2 = 0.f;
        #pragma unroll
        for (int ky = 0; ky < 3; ky++) {
            #pragma unroll
            for (int kx = 0; kx < 3; kx++) {
                a  += wa[ky*3+kx] * ya[ky][o+kx];
                g2 += wb[ky*3+kx] * yb[ky][o+kx];
            }
        }
        float ge = 0.5f * a * (1.f + erff(a * 0.70710678118654752f));
        g_gg[((size_t)(bb*HH + r)*WW + xseg + o)*512 + c] = __float2bfloat16(ge * g2);
    }
}

// ================= K6: pout GEMM bf16 (131072 x 192 x 512) + residual -> NCHW ==================
#define SPP 132
__global__ __launch_bounds__(256,2) void k_pout_b(float* __restrict__ outp) {
    __shared__ __align__(16) float smem_f[8448];
    __nv_bfloat16* As = (__nv_bfloat16*)smem_f;
    __nv_bfloat16* Bs = (__nv_bfloat16*)(smem_f + 5120);
    float* Cs = smem_f;
    int pt = blockIdx.y*128;
    int ct = blockIdx.x*64;
    int tid = threadIdx.x;
    int lane = tid & 31;
    int warp = tid >> 5;
    int m0 = (warp & 3)*32;
    int n0 = (warp >> 2)*32;
    float acc[2][4][4] = {};

    pout_load(As, Bs, pt, ct, 0, tid);

    for (int ch = 0; ch < 16; ch++) {
        asm volatile("cp.async.wait_group 0;" ::: "memory");
        __syncthreads();
        if (ch < 15) {
            int st = (ch+1) & 1;
            pout_load(As + st*5120, Bs + st*2560, pt, ct, (ch+1)*32, tid);
        }
        u32 ab = sptr(As + (ch & 1)*5120);
        u32 bbs = sptr(Bs + (ch & 1)*2560);
        #pragma unroll
        for (int ks = 0; ks < 2; ks++) {
            u32 av[2][4];
            u32 bv[4][2];
            #pragma unroll
            for (int mt = 0; mt < 2; mt++) {
                int row = m0 + mt*16 + (lane & 15);
                u32 ad = ab + (row*40 + ((lane >> 4) & 1)*8 + ks*16)*2;
                ldsm4(av[mt][0], av[mt][1], av[mt][2], av[mt][3], ad);
            }
            #pragma unroll
            for (int n2 = 0; n2 < 2; n2++) {
                int row = n0 + n2*16 + (lane & 7) + ((lane >> 4) & 1)*8;
                u32 ad = bbs + (row*40 + ((lane >> 3) & 1)*8 + ks*16)*2;
                u32 r0;
                u32 r1;
                u32 r2;
                u32 r3;
                ldsm4(r0, r1, r2, r3, ad);
                bv[n2*2+0][0] = r0;
                bv[n2*2+0][1] = r1;
                bv[n2*2+1][0] = r2;
                bv[n2*2+1][1] = r3;
            }
            #pragma unroll
            for (int mt = 0; mt < 2; mt++) {
                #pragma unroll
                for (int nt = 0; nt < 4; nt++) {
                    mma_bf16(acc[mt][nt][0], acc[mt][nt][1], acc[mt][nt][2], acc[mt][nt][3],
                             av[mt][0], av[mt][1], av[mt][2], av[mt][3], bv[nt][0], bv[nt][1]);
                }
            }
        }
    }
    __syncthreads();

    int lr = lane >> 2;
    int lc = lane & 3;
    #pragma unroll
    for (int mt = 0; mt < 2; mt++) {
        int row = m0 + mt*16 + lr;
        #pragma unroll
        for (int nt = 0; nt < 4; nt++) {
            int col = n0 + nt*8 + 2*lc;
            Cs[col*SPP + row] = acc[mt][nt][0];
            Cs[(col+1)*SPP + row] = acc[mt][nt][1];
            Cs[col*SPP + row + 8] = acc[mt][nt][2];
            Cs[(col+1)*SPP + row + 8] = acc[mt][nt][3];
        }
    }
    __syncthreads();
    for (int e = tid; e < 2048; e += 256) {
        int p = e >> 4;
        int c4 = e & 15;
        float4 v = *(const float4*)&g_x2[(size_t)(pt + p)*C + ct + c4*4];
        Cs[(c4*4+0)*SPP + p] += v.x;
        Cs[(c4*4+1)*SPP + p] += v.y;
        Cs[(c4*4+2)*SPP + p] += v.z;
        Cs[(c4*4+3)*SPP + p] += v.w;
    }
    __syncthreads();
    int bb = pt >> 16;
    int hw0 = pt & 65535;
    for (int e = tid; e < 2048; e += 256) {
        int c = e >> 5;
        int p4 = e & 31;
        float4 v = *(const float4*)&Cs[c*SPP + p4*4];
        *(float4*)&outp[((size_t)(bb*C + ct + c))*HW + hw0 + p4*4] = v;
    }
}

// ================= launch ==================
extern "C" void kernel_launch(void* const* d_in, const int* in_sizes, int n_in,
                              void* d_out, int out_size) {
    const float* x      = (const float*)d_in[0];
    const float* n1w    = (const float*)d_in[1];
    const float* n1b    = (const float*)d_in[2];
    const float* qkv_w  = (const float*)d_in[3];
    const float* rpb    = (const float*)d_in[4];
    const float* proj_w = (const float*)d_in[5];
    const float* proj_b = (const float*)d_in[6];
    const float* n2w    = (const float*)d_in[7];
    const float* n2b    = (const float*)d_in[8];
    const float* pin_w  = (const float*)d_in[9];
    const float* dw_w   = (const float*)d_in[10];
    const float* pout_w = (const float*)d_in[11];
    float* outp = (float*)d_out;

    const int attn_smem = (192*XT + 3*64*SQ + 64*XT) * 4;
    cudaFuncSetAttribute(k_attn, cudaFuncAttributeMaxDynamicSharedMemorySize, attn_smem);

    k_cvt_pin<<<(HID2*C + 255)/256, 256>>>(pin_w);
    k_cvt_pout<<<(C*512 + 255)/256, 256>>>(pout_w);
    k_ln1  <<<NPIX/32, 256>>>(x, n1w, n1b);
    k_attn <<<2048, 256, attn_smem>>>(qkv_w, rpb, proj_w, proj_b);
    k_ln2  <<<NPIX/8, 256>>>(n2w, n2b);
    k_pin_b<<<dim3(8, NPIX/128), 256>>>();
    k_dw   <<<dim3(BATCH*HH*(WW/4), 2), 256>>>(dw_w);
    k_pout_b<<<dim3(3, NPIX/128), 256>>>(outp);
}

// round 7
// speedup vs baseline: 3.2794x; 2.1759x over previous
#include <cuda_runtime.h>
#include <cuda_bf16.h>
#include <stdint.h>
#include <math.h>

typedef unsigned int u32;

#define BATCH 2
#define C 192
#define HH 256
#define WW 256
#define HW (HH*WW)
#define NPIX (BATCH*HW)
#define NH 8
#define HD 24
#define WS 8
#define SS 4
#define HID 510
#define HID2 1020

// ---- scratch ----
__device__ float g_xt[NPIX*C];                        // x in BHWC (residual)
__device__ float g_x2[NPIX*C];                        // x + attn (BHWC)
__device__ __nv_bfloat16 g_xnb[(size_t)NPIX*C];       // LN1 out, bf16, window-token order
__device__ float g_qkv[(size_t)NPIX*576];             // QKV fp32, token order
__device__ __nv_bfloat16 g_attnb[(size_t)NPIX*C];     // attention out bf16, token order
__device__ __nv_bfloat16 g_ynb[(size_t)NPIX*C];
__device__ __nv_bfloat16 g_y[(size_t)NPIX*HID2];
__device__ __nv_bfloat16 g_gg[(size_t)NPIX*512];
__device__ __nv_bfloat16 g_qkvw[576*C];
__device__ __nv_bfloat16 g_projw[C*C];
__device__ __nv_bfloat16 g_pinb[HID2*C];
__device__ __nv_bfloat16 g_poutb[C*512];

__device__ __forceinline__ u32 sptr(const void* p) {
    return (u32)__cvta_generic_to_shared(p);
}
__device__ __forceinline__ void cpa16(u32 dst, const void* src, bool full) {
    int sz = full ? 16 : 0;
    asm volatile("cp.async.cg.shared.global [%0], [%1], 16, %2;" :: "r"(dst), "l"(src), "r"(sz));
}
__device__ __forceinline__ void ldsm4(u32& r0, u32& r1, u32& r2, u32& r3, u32 a) {
    asm volatile("ldmatrix.sync.aligned.m8n8.x4.shared.b16 {%0,%1,%2,%3}, [%4];"
        : "=r"(r0), "=r"(r1), "=r"(r2), "=r"(r3) : "r"(a));
}
__device__ __forceinline__ void mma_bf16(float& c0, float& c1, float& c2, float& c3,
    u32 a0, u32 a1, u32 a2, u32 a3, u32 b0, u32 b1) {
    asm volatile("mma.sync.aligned.m16n8k16.row.col.f32.bf16.bf16.f32 "
        "{%0,%1,%2,%3}, {%4,%5,%6,%7}, {%8,%9}, {%0,%1,%2,%3};"
        : "+f"(c0), "+f"(c1), "+f"(c2), "+f"(c3)
        : "r"(a0), "r"(a1), "r"(a2), "r"(a3), "r"(b0), "r"(b1));
}

// ================= weight converts ==================
__global__ void k_cvt_qkvw(const float* __restrict__ src) {
    int i = blockIdx.x*256 + threadIdx.x;
    if (i < 576*C) {
        g_qkvw[i] = __float2bfloat16(src[i]);
    }
}
__global__ void k_cvt_projw(const float* __restrict__ src) {
    int i = blockIdx.x*256 + threadIdx.x;
    if (i < C*C) {
        g_projw[i] = __float2bfloat16(src[i]);
    }
}
__global__ void k_cvt_pin(const float* __restrict__ src) {
    int i = blockIdx.x*256 + threadIdx.x;
    if (i < HID2*C) {
        g_pinb[i] = __float2bfloat16(src[i]);
    }
}
__global__ void k_cvt_pout(const float* __restrict__ src) {
    int i = blockIdx.x*256 + threadIdx.x;
    if (i < C*512) {
        int o = i >> 9;
        int k = i & 511;
        g_poutb[i] = __float2bfloat16(k < HID ? src[o*HID + k] : 0.f);
    }
}

// ================= K1: LN1 + transpose + window-permuted bf16 ==================
__global__ __launch_bounds__(256) void k_ln1(const float* __restrict__ x,
        const float* __restrict__ w, const float* __restrict__ b) {
    __shared__ float s[C*33];
    __shared__ float smu[32];
    __shared__ float srv[32];
    __shared__ int slot_s[32];
    int pix0 = blockIdx.x * 32;
    int bb = pix0 / HW;
    int hw0 = pix0 % HW;
    for (int e = threadIdx.x; e < C*32; e += 256) {
        int c = e >> 5;
        int p = e & 31;
        s[c*33 + p] = x[(size_t)(bb*C + c)*HW + hw0 + p];
    }
    __syncthreads();
    if (threadIdx.x < 32) {
        int p = threadIdx.x;
        float sum = 0.f;
        float sq = 0.f;
        for (int c = 0; c < C; c++) {
            float v = s[c*33+p];
            sum += v;
            sq += v*v;
        }
        float mu = sum / C;
        float var = sq / C - mu*mu;
        smu[p] = mu;
        srv[p] = rsqrtf(var + 1e-5f);
        int hw = hw0 + p;
        int r = hw >> 8;
        int cc = hw & 255;
        int sr = (r - SS + 256) & 255;
        int sc = (cc - SS + 256) & 255;
        slot_s[p] = (((bb << 10) + ((sr >> 3) << 5) + (sc >> 3)) << 6) + ((sr & 7) << 3) + (sc & 7);
    }
    __syncthreads();
    for (int e = threadIdx.x; e < C*32; e += 256) {
        int p = e / C;
        int c = e % C;
        float v = s[c*33 + p];
        g_xt[(pix0 + p)*C + c] = v;
        float ln = (v - smu[p]) * srv[p] * w[c] + b[c];
        g_xnb[(size_t)slot_s[p]*C + c] = __float2bfloat16(ln);
    }
}

// ================= tile loaders ==================
__device__ __forceinline__ void qkv_load(__nv_bfloat16* Adst, __nv_bfloat16* Bdst,
                                         int pt, int ot, int k0, int tid) {
    #pragma unroll
    for (int i = 0; i < 2; i++) {
        int e = tid + i*256;
        int row = e >> 2;
        int seg = e & 3;
        cpa16(sptr(Adst + row*40 + seg*8), g_xnb + (size_t)(pt + row)*C + k0 + seg*8, true);
        int og = ot + row;
        bool ok = og < 576;
        cpa16(sptr(Bdst + row*40 + seg*8), g_qkvw + (size_t)(ok ? og : 0)*C + k0 + seg*8, ok);
    }
    asm volatile("cp.async.commit_group;" ::: "memory");
}

__device__ __forceinline__ void proj_load(__nv_bfloat16* Adst, __nv_bfloat16* Bdst,
                                          int pt, int ct, int k0, int tid) {
    #pragma unroll
    for (int i = 0; i < 2; i++) {
        int e = tid + i*256;
        int row = e >> 2;
        int seg = e & 3;
        cpa16(sptr(Adst + row*40 + seg*8), g_attnb + (size_t)(pt + row)*C + k0 + seg*8, true);
    }
    int row = tid >> 2;
    int seg = tid & 3;
    cpa16(sptr(Bdst + row*40 + seg*8), g_projw + (size_t)(ct + row)*C + k0 + seg*8, true);
    asm volatile("cp.async.commit_group;" ::: "memory");
}

__device__ __forceinline__ void pin_load(__nv_bfloat16* Adst, __nv_bfloat16* Bdst,
                                         int pt, int ot, int k0, int tid) {
    #pragma unroll
    for (int i = 0; i < 2; i++) {
        int e = tid + i*256;
        int row = e >> 2;
        int seg = e & 3;
        cpa16(sptr(Adst + row*40 + seg*8), g_ynb + (size_t)(pt + row)*C + k0 + seg*8, true);
        int og = ot + row;
        bool ok = og < HID2;
        cpa16(sptr(Bdst + row*40 + seg*8), g_pinb + (size_t)(ok ? og : 0)*C + k0 + seg*8, ok);
    }
    asm volatile("cp.async.commit_group;" ::: "memory");
}

__device__ __forceinline__ void pout_load(__nv_bfloat16* Adst, __nv_bfloat16* Bdst,
                                          int pt, int ct, int k0, int tid) {
    #pragma unroll
    for (int i = 0; i < 2; i++) {
        int e = tid + i*256;
        int row = e >> 2;
        int seg = e & 3;
        cpa16(sptr(Adst + row*40 + seg*8), g_gg + (size_t)(pt + row)*512 + k0 + seg*8, true);
    }
    int row = tid >> 2;
    int seg = tid & 3;
    cpa16(sptr(Bdst + row*40 + seg*8), g_poutb + (size_t)(ct + row)*512 + k0 + seg*8, true);
    asm volatile("cp.async.commit_group;" ::: "memory");
}

// ================= K2a: QKV GEMM bf16 (131072 x 576 x 192) -> fp32 ==================
__global__ __launch_bounds__(256,2) void k_qkv_b() {
    __shared__ __align__(16) __nv_bfloat16 As[2][5120];
    __shared__ __align__(16) __nv_bfloat16 Bs[2][5120];
    int pt = blockIdx.y*128;
    int ot = blockIdx.x*128;
    int tid = threadIdx.x;
    int lane = tid & 31;
    int warp = tid >> 5;
    int m0 = (warp >> 2)*64;
    int n0 = (warp & 3)*32;
    float acc[4][4][4] = {};

    qkv_load(As[0], Bs[0], pt, ot, 0, tid);

    for (int ch = 0; ch < 6; ch++) {
        asm volatile("cp.async.wait_group 0;" ::: "memory");
        __syncthreads();
        if (ch < 5) {
            qkv_load(As[(ch+1)&1], Bs[(ch+1)&1], pt, ot, (ch+1)*32, tid);
        }
        u32 ab = sptr(As[ch & 1]);
        u32 bbs = sptr(Bs[ch & 1]);
        #pragma unroll
        for (int ks = 0; ks < 2; ks++) {
            u32 av[4][4];
            u32 bv[4][2];
            #pragma unroll
            for (int mt = 0; mt < 4; mt++) {
                int row = m0 + mt*16 + (lane & 15);
                u32 ad = ab + (row*40 + ((lane >> 4) & 1)*8 + ks*16)*2;
                ldsm4(av[mt][0], av[mt][1], av[mt][2], av[mt][3], ad);
            }
            #pragma unroll
            for (int n2 = 0; n2 < 2; n2++) {
                int row = n0 + n2*16 + (lane & 7) + ((lane >> 4) & 1)*8;
                u32 ad = bbs + (row*40 + ((lane >> 3) & 1)*8 + ks*16)*2;
                u32 r0;
                u32 r1;
                u32 r2;
                u32 r3;
                ldsm4(r0, r1, r2, r3, ad);
                bv[n2*2+0][0] = r0;
                bv[n2*2+0][1] = r1;
                bv[n2*2+1][0] = r2;
                bv[n2*2+1][1] = r3;
            }
            #pragma unroll
            for (int mt = 0; mt < 4; mt++) {
                #pragma unroll
                for (int nt = 0; nt < 4; nt++) {
                    mma_bf16(acc[mt][nt][0], acc[mt][nt][1], acc[mt][nt][2], acc[mt][nt][3],
                             av[mt][0], av[mt][1], av[mt][2], av[mt][3], bv[nt][0], bv[nt][1]);
                }
            }
        }
    }

    const float qscale = 0.20412414523193154f;
    int lr = lane >> 2;
    int lc = lane & 3;
    #pragma unroll
    for (int mt = 0; mt < 4; mt++) {
        int row = pt + m0 + mt*16 + lr;
        #pragma unroll
        for (int nt = 0; nt < 4; nt++) {
            int col = ot + n0 + nt*8 + 2*lc;
            if (col < 576) {
                float s = (col < C) ? qscale : 1.f;
                float2 v0;
                v0.x = acc[mt][nt][0] * s;
                v0.y = acc[mt][nt][1] * s;
                *(float2*)&g_qkv[(size_t)row*576 + col] = v0;
                float2 v1;
                v1.x = acc[mt][nt][2] * s;
                v1.y = acc[mt][nt][3] * s;
                *(float2*)&g_qkv[(size_t)(row+8)*576 + col] = v1;
            }
        }
    }
}

// ================= K2b: per-window attention core ==================
#define QP 580
__global__ __launch_bounds__(256,1) void k_wattn(const float* __restrict__ rpb) {
    extern __shared__ float sm[];
    float* QKV = sm;              // [64][QP]
    float* As  = sm + 64*QP;      // [64][68]
    __shared__ float rpb_s[225*NH];
    __shared__ int lab[64];

    int tid = threadIdx.x;
    int widx = blockIdx.x;
    int pix0 = widx * 64;
    int wy = (widx >> 5) & 31;
    int wx = widx & 31;

    if (tid < 64) {
        int i1 = tid >> 3;
        int j1 = tid & 7;
        int sr = wy*8 + i1;
        int sc = wx*8 + j1;
        lab[tid] = ((sr >= HH-WS) + (sr >= HH-SS))*3 + ((sc >= WW-WS) + (sc >= WW-SS));
    }
    for (int e = tid; e < 225*NH; e += 256) {
        rpb_s[e] = rpb[e];
    }
    for (int e = tid; e < 64*144; e += 256) {
        int row = e / 144;
        int seg = e - row*144;
        *(float4*)&QKV[row*QP + seg*4] = *(const float4*)(g_qkv + (size_t)(pix0 + row)*576 + seg*4);
    }
    __syncthreads();

    int tx = tid & 15;
    int ty = tid >> 4;
    int m0 = tx*4;
    int n0 = ty*4;

    for (int h = 0; h < NH; h++) {
        int off = h*HD;
        float a[4][4] = {};
        #pragma unroll
        for (int d4 = 0; d4 < 6; d4++) {
            float4 q[4];
            float4 kv[4];
            #pragma unroll
            for (int i = 0; i < 4; i++) {
                q[i] = *(const float4*)&QKV[(n0+i)*QP + off + d4*4];
            }
            #pragma unroll
            for (int j = 0; j < 4; j++) {
                kv[j] = *(const float4*)&QKV[(m0+j)*QP + C + off + d4*4];
            }
            #pragma unroll
            for (int i = 0; i < 4; i++) {
                #pragma unroll
                for (int j = 0; j < 4; j++) {
                    a[i][j] += q[i].x*kv[j].x + q[i].y*kv[j].y + q[i].z*kv[j].z + q[i].w*kv[j].w;
                }
            }
        }
        #pragma unroll
        for (int i = 0; i < 4; i++) {
            int n = n0 + i;
            int i1 = n >> 3;
            int j1 = n & 7;
            #pragma unroll
            for (int j = 0; j < 4; j++) {
                int m = m0 + j;
                int i2 = m >> 3;
                int j2 = m & 7;
                float v = a[i][j] + rpb_s[((i1-i2+7)*15 + (j1-j2+7))*NH + h];
                if (lab[n] != lab[m]) {
                    v -= 100.f;
                }
                As[n*68 + m] = v;
            }
        }
        __syncthreads();
        {
            int row = tid >> 2;
            float* rp = &As[row*68 + (tid & 3)*16];
            float mx = rp[0];
            #pragma unroll
            for (int t = 1; t < 16; t++) {
                mx = fmaxf(mx, rp[t]);
            }
            mx = fmaxf(mx, __shfl_xor_sync(0xffffffffu, mx, 1));
            mx = fmaxf(mx, __shfl_xor_sync(0xffffffffu, mx, 2));
            float s2 = 0.f;
            #pragma unroll
            for (int t = 0; t < 16; t++) {
                float e2 = expf(rp[t] - mx);
                rp[t] = e2;
                s2 += e2;
            }
            s2 += __shfl_xor_sync(0xffffffffu, s2, 1);
            s2 += __shfl_xor_sync(0xffffffffu, s2, 2);
            float inv = 1.f / s2;
            #pragma unroll
            for (int t = 0; t < 16; t++) {
                rp[t] *= inv;
            }
        }
        __syncthreads();
        for (int e = tid; e < 384; e += 256) {
            int n = e / 6;
            int d4 = e % 6;
            float4 acc2 = make_float4(0.f, 0.f, 0.f, 0.f);
            const float* arow = &As[n*68];
            #pragma unroll 8
            for (int m = 0; m < 64; m++) {
                float av = arow[m];
                float4 v = *(const float4*)&QKV[m*QP + 2*C + off + d4*4];
                acc2.x += av*v.x;
                acc2.y += av*v.y;
                acc2.z += av*v.z;
                acc2.w += av*v.w;
            }
            __nv_bfloat162 o0;
            o0.x = __float2bfloat16(acc2.x);
            o0.y = __float2bfloat16(acc2.y);
            __nv_bfloat162 o1;
            o1.x = __float2bfloat16(acc2.z);
            o1.y = __float2bfloat16(acc2.w);
            size_t ob = (size_t)(pix0 + n)*C + off + d4*4;
            *(__nv_bfloat162*)&g_attnb[ob] = o0;
            *(__nv_bfloat162*)&g_attnb[ob + 2] = o1;
        }
        __syncthreads();
    }
}

// ================= K2c: proj GEMM bf16 (131072 x 192 x 192) + bias + residual ==================
__global__ __launch_bounds__(256,2) void k_proj_b(const float* __restrict__ pb) {
    __shared__ __align__(16) __nv_bfloat16 As[2][5120];
    __shared__ __align__(16) __nv_bfloat16 Bs[2][2560];
    int pt = blockIdx.y*128;
    int ct = blockIdx.x*64;
    int tid = threadIdx.x;
    int lane = tid & 31;
    int warp = tid >> 5;
    int m0 = (warp & 3)*32;
    int n0 = (warp >> 2)*32;
    float acc[2][4][4] = {};

    proj_load(As[0], Bs[0], pt, ct, 0, tid);

    for (int ch = 0; ch < 6; ch++) {
        asm volatile("cp.async.wait_group 0;" ::: "memory");
        __syncthreads();
        if (ch < 5) {
            proj_load(As[(ch+1)&1], Bs[(ch+1)&1], pt, ct, (ch+1)*32, tid);
        }
        u32 ab = sptr(As[ch & 1]);
        u32 bbs = sptr(Bs[ch & 1]);
        #pragma unroll
        for (int ks = 0; ks < 2; ks++) {
            u32 av[2][4];
            u32 bv[4][2];
            #pragma unroll
            for (int mt = 0; mt < 2; mt++) {
                int row = m0 + mt*16 + (lane & 15);
                u32 ad = ab + (row*40 + ((lane >> 4) & 1)*8 + ks*16)*2;
                ldsm4(av[mt][0], av[mt][1], av[mt][2], av[mt][3], ad);
            }
            #pragma unroll
            for (int n2 = 0; n2 < 2; n2++) {
                int row = n0 + n2*16 + (lane & 7) + ((lane >> 4) & 1)*8;
                u32 ad = bbs + (row*40 + ((lane >> 3) & 1)*8 + ks*16)*2;
                u32 r0;
                u32 r1;
                u32 r2;
                u32 r3;
                ldsm4(r0, r1, r2, r3, ad);
                bv[n2*2+0][0] = r0;
                bv[n2*2+0][1] = r1;
                bv[n2*2+1][0] = r2;
                bv[n2*2+1][1] = r3;
            }
            #pragma unroll
            for (int mt = 0; mt < 2; mt++) {
                #pragma unroll
                for (int nt = 0; nt < 4; nt++) {
                    mma_bf16(acc[mt][nt][0], acc[mt][nt][1], acc[mt][nt][2], acc[mt][nt][3],
                             av[mt][0], av[mt][1], av[mt][2], av[mt][3], bv[nt][0], bv[nt][1]);
                }
            }
        }
    }

    int lr = lane >> 2;
    int lc = lane & 3;
    #pragma unroll
    for (int mt = 0; mt < 2; mt++) {
        #pragma unroll
        for (int half = 0; half < 2; half++) {
            int row = pt + m0 + mt*16 + lr + half*8;
            int bb = row >> 16;
            int widx = (row >> 6) & 1023;
            int tok = row & 63;
            int r = (((widx >> 5) << 3) + (tok >> 3) + SS) & 255;
            int c2 = (((widx & 31) << 3) + (tok & 7) + SS) & 255;
            int gbase = ((bb*HH + r)*WW + c2)*C;
            #pragma unroll
            for (int nt = 0; nt < 4; nt++) {
                int col = ct + n0 + nt*8 + 2*lc;
                float2 v;
                v.x = acc[mt][nt][half*2+0] + pb[col] + g_xt[gbase + col];
                v.y = acc[mt][nt][half*2+1] + pb[col+1] + g_xt[gbase + col + 1];
                *(float2*)&g_x2[gbase + col] = v;
            }
        }
    }
}

// ================= K3: LN2 -> bf16 ==================
__global__ __launch_bounds__(256) void k_ln2(const float* __restrict__ w,
                                             const float* __restrict__ b) {
    int pix = blockIdx.x*8 + (threadIdx.x >> 5);
    int lane = threadIdx.x & 31;
    const float* row = g_x2 + (size_t)pix*C;
    float v[6];
    float sum = 0.f;
    float sq = 0.f;
    #pragma unroll
    for (int i = 0; i < 6; i++) {
        v[i] = row[lane + 32*i];
        sum += v[i];
        sq += v[i]*v[i];
    }
    #pragma unroll
    for (int o = 16; o; o >>= 1) {
        sum += __shfl_xor_sync(0xffffffffu, sum, o);
        sq  += __shfl_xor_sync(0xffffffffu, sq, o);
    }
    float mu = sum / C;
    float rv = rsqrtf(sq / C - mu*mu + 1e-5f);
    __nv_bfloat16* outp = g_ynb + (size_t)pix*C;
    #pragma unroll
    for (int i = 0; i < 6; i++) {
        int c = lane + 32*i;
        outp[c] = __float2bfloat16((v[i]-mu)*rv*w[c] + b[c]);
    }
}

// ================= K4: pin GEMM bf16 (131072 x 1020 x 192) ==================
__global__ __launch_bounds__(256,2) void k_pin_b() {
    __shared__ __align__(16) __nv_bfloat16 As[2][5120];
    __shared__ __align__(16) __nv_bfloat16 Bs[2][5120];
    int pt = blockIdx.y*128;
    int ot = blockIdx.x*128;
    int tid = threadIdx.x;
    int lane = tid & 31;
    int warp = tid >> 5;
    int m0 = (warp >> 2)*64;
    int n0 = (warp & 3)*32;
    float acc[4][4][4] = {};

    pin_load(As[0], Bs[0], pt, ot, 0, tid);

    for (int ch = 0; ch < 6; ch++) {
        asm volatile("cp.async.wait_group 0;" ::: "memory");
        __syncthreads();
        if (ch < 5) {
            pin_load(As[(ch+1)&1], Bs[(ch+1)&1], pt, ot, (ch+1)*32, tid);
        }
        u32 ab = sptr(As[ch & 1]);
        u32 bbs = sptr(Bs[ch & 1]);
        #pragma unroll
        for (int ks = 0; ks < 2; ks++) {
            u32 av[4][4];
            u32 bv[4][2];
            #pragma unroll
            for (int mt = 0; mt < 4; mt++) {
                int row = m0 + mt*16 + (lane & 15);
                u32 ad = ab + (row*40 + ((lane >> 4) & 1)*8 + ks*16)*2;
                ldsm4(av[mt][0], av[mt][1], av[mt][2], av[mt][3], ad);
            }
            #pragma unroll
            for (int n2 = 0; n2 < 2; n2++) {
                int row = n0 + n2*16 + (lane & 7) + ((lane >> 4) & 1)*8;
                u32 ad = bbs + (row*40 + ((lane >> 3) & 1)*8 + ks*16)*2;
                u32 r0;
                u32 r1;
                u32 r2;
                u32 r3;
                ldsm4(r0, r1, r2, r3, ad);
                bv[n2*2+0][0] = r0;
                bv[n2*2+0][1] = r1;
                bv[n2*2+1][0] = r2;
                bv[n2*2+1][1] = r3;
            }
            #pragma unroll
            for (int mt = 0; mt < 4; mt++) {
                #pragma unroll
                for (int nt = 0; nt < 4; nt++) {
                    mma_bf16(acc[mt][nt][0], acc[mt][nt][1], acc[mt][nt][2], acc[mt][nt][3],
                             av[mt][0], av[mt][1], av[mt][2], av[mt][3], bv[nt][0], bv[nt][1]);
                }
            }
        }
    }

    int lr = lane >> 2;
    int lc = lane & 3;
    #pragma unroll
    for (int mt = 0; mt < 4; mt++) {
        int row = pt + m0 + mt*16 + lr;
        #pragma unroll
        for (int nt = 0; nt < 4; nt++) {
            int col = ot + n0 + nt*8 + 2*lc;
            if (col < HID2) {
                __nv_bfloat162 v0;
                v0.x = __float2bfloat16(acc[mt][nt][0]);
                v0.y = __float2bfloat16(acc[mt][nt][1]);
                *(__nv_bfloat162*)&g_y[(size_t)row*HID2 + col] = v0;
                __nv_bfloat162 v1;
                v1.x = __float2bfloat16(acc[mt][nt][2]);
                v1.y = __float2bfloat16(acc[mt][nt][3]);
                *(__nv_bfloat162*)&g_y[(size_t)(row+8)*HID2 + col] = v1;
            }
        }
    }
}

// ================= K5: depthwise 3x3 + gated GELU (bf16 in/out) ==================
__global__ __launch_bounds__(256) void k_dw(const float* __restrict__ dw) {
    int bx = blockIdx.x;
    int c = blockIdx.y * 256 + threadIdx.x;
    int xseg = (bx & 63) * 4;
    int r = (bx >> 6) & 255;
    int bb = bx >> 14;
    if (blockIdx.y == 0 && threadIdx.x < 2) {
        #pragma unroll
        for (int o = 0; o < 4; o++) {
            g_gg[((size_t)(bb*HH + r)*WW + xseg + o)*512 + HID + threadIdx.x] = __float2bfloat16(0.f);
        }
    }
    if (c >= HID) {
        return;
    }
    float ya[3][6];
    float yb[3][6];
    #pragma unroll
    for (int dy = 0; dy < 3; dy++) {
        int rowi = r + dy - 1;
        bool rok = (unsigned)rowi < 256u;
        #pragma unroll
        for (int dx = 0; dx < 6; dx++) {
            int col = xseg + dx - 1;
            bool ok = rok && ((unsigned)col < 256u);
            size_t base = ((size_t)(bb*HH + rowi)*WW + col)*HID2;
            ya[dy][dx] = ok ? __bfloat162float(g_y[base + c]) : 0.f;
            yb[dy][dx] = ok ? __bfloat162float(g_y[base + c + HID]) : 0.f;
        }
    }
    float wa[9];
    float wb[9];
    #pragma unroll
    for (int t = 0; t < 9; t++) {
        wa[t] = dw[c*9 + t];
        wb[t] = dw[(c + HID)*9 + t];
    }
    #pragma unroll
    for (int o = 0; o < 4; o++) {
        float a = 0.f;
        float g2 = 0.f;
        #pragma unroll
        for (int ky = 0; ky < 3; ky++) {
            #pragma unroll
            for (int kx = 0; kx < 3; kx++) {
                a  += wa[ky*3+kx] * ya[ky][o+kx];
                g2 += wb[ky*3+kx] * yb[ky][o+kx];
            }
        }
        float ge = 0.5f * a * (1.f + erff(a * 0.70710678118654752f));
        g_gg[((size_t)(bb*HH + r)*WW + xseg + o)*512 + c] = __float2bfloat16(ge * g2);
    }
}

// ================= K6: pout GEMM bf16 (131072 x 192 x 512) + residual -> NCHW ==================
#define SPP 132
__global__ __launch_bounds__(256,2) void k_pout_b(float* __restrict__ outp) {
    __shared__ __align__(16) float smem_f[8448];
    __nv_bfloat16* As = (__nv_bfloat16*)smem_f;
    __nv_bfloat16* Bs = (__nv_bfloat16*)(smem_f + 5120);
    float* Cs = smem_f;
    int pt = blockIdx.y*128;
    int ct = blockIdx.x*64;
    int tid = threadIdx.x;
    int lane = tid & 31;
    int warp = tid >> 5;
    int m0 = (warp & 3)*32;
    int n0 = (warp >> 2)*32;
    float acc[2][4][4] = {};

    pout_load(As, Bs, pt, ct, 0, tid);

    for (int ch = 0; ch < 16; ch++) {
        asm volatile("cp.async.wait_group 0;" ::: "memory");
        __syncthreads();
        if (ch < 15) {
            int st = (ch+1) & 1;
            pout_load(As + st*5120, Bs + st*2560, pt, ct, (ch+1)*32, tid);
        }
        u32 ab = sptr(As + (ch & 1)*5120);
        u32 bbs = sptr(Bs + (ch & 1)*2560);
        #pragma unroll
        for (int ks = 0; ks < 2; ks++) {
            u32 av[2][4];
            u32 bv[4][2];
            #pragma unroll
            for (int mt = 0; mt < 2; mt++) {
                int row = m0 + mt*16 + (lane & 15);
                u32 ad = ab + (row*40 + ((lane >> 4) & 1)*8 + ks*16)*2;
                ldsm4(av[mt][0], av[mt][1], av[mt][2], av[mt][3], ad);
            }
            #pragma unroll
            for (int n2 = 0; n2 < 2; n2++) {
                int row = n0 + n2*16 + (lane & 7) + ((lane >> 4) & 1)*8;
                u32 ad = bbs + (row*40 + ((lane >> 3) & 1)*8 + ks*16)*2;
                u32 r0;
                u32 r1;
                u32 r2;
                u32 r3;
                ldsm4(r0, r1, r2, r3, ad);
                bv[n2*2+0][0] = r0;
                bv[n2*2+0][1] = r1;
                bv[n2*2+1][0] = r2;
                bv[n2*2+1][1] = r3;
            }
            #pragma unroll
            for (int mt = 0; mt < 2; mt++) {
                #pragma unroll
                for (int nt = 0; nt < 4; nt++) {
                    mma_bf16(acc[mt][nt][0], acc[mt][nt][1], acc[mt][nt][2], acc[mt][nt][3],
                             av[mt][0], av[mt][1], av[mt][2], av[mt][3], bv[nt][0], bv[nt][1]);
                }
            }
        }
    }
    __syncthreads();

    int lr = lane >> 2;
    int lc = lane & 3;
    #pragma unroll
    for (int mt = 0; mt < 2; mt++) {
        int row = m0 + mt*16 + lr;
        #pragma unroll
        for (int nt = 0; nt < 4; nt++) {
            int col = n0 + nt*8 + 2*lc;
            Cs[col*SPP + row] = acc[mt][nt][0];
            Cs[(col+1)*SPP + row] = acc[mt][nt][1];
            Cs[col*SPP + row + 8] = acc[mt][nt][2];
            Cs[(col+1)*SPP + row + 8] = acc[mt][nt][3];
        }
    }
    __syncthreads();
    for (int e = tid; e < 2048; e += 256) {
        int p = e >> 4;
        int c4 = e & 15;
        float4 v = *(const float4*)&g_x2[(size_t)(pt + p)*C + ct + c4*4];
        Cs[(c4*4+0)*SPP + p] += v.x;
        Cs[(c4*4+1)*SPP + p] += v.y;
        Cs[(c4*4+2)*SPP + p] += v.z;
        Cs[(c4*4+3)*SPP + p] += v.w;
    }
    __syncthreads();
    int bb = pt >> 16;
    int hw0 = pt & 65535;
    for (int e = tid; e < 2048; e += 256) {
        int c = e >> 5;
        int p4 = e & 31;
        float4 v = *(const float4*)&Cs[c*SPP + p4*4];
        *(float4*)&outp[((size_t)(bb*C + ct + c))*HW + hw0 + p4*4] = v;
    }
}

// ================= launch ==================
extern "C" void kernel_launch(void* const* d_in, const int* in_sizes, int n_in,
                              void* d_out, int out_size) {
    const float* x      = (const float*)d_in[0];
    const float* n1w    = (const float*)d_in[1];
    const float* n1b    = (const float*)d_in[2];
    const float* qkv_w  = (const float*)d_in[3];
    const float* rpb    = (const float*)d_in[4];
    const float* proj_w = (const float*)d_in[5];
    const float* proj_b = (const float*)d_in[6];
    const float* n2w    = (const float*)d_in[7];
    const float* n2b    = (const float*)d_in[8];
    const float* pin_w  = (const float*)d_in[9];
    const float* dw_w   = (const float*)d_in[10];
    const float* pout_w = (const float*)d_in[11];
    float* outp = (float*)d_out;

    const int wattn_smem = (64*QP + 64*68) * 4;   // 165888
    cudaFuncSetAttribute(k_wattn, cudaFuncAttributeMaxDynamicSharedMemorySize, wattn_smem);

    k_cvt_qkvw<<<(576*C + 255)/256, 256>>>(qkv_w);
    k_cvt_projw<<<(C*C + 255)/256, 256>>>(proj_w);
    k_cvt_pin<<<(HID2*C + 255)/256, 256>>>(pin_w);
    k_cvt_pout<<<(C*512 + 255)/256, 256>>>(pout_w);
    k_ln1   <<<NPIX/32, 256>>>(x, n1w, n1b);
    k_qkv_b <<<dim3(5, NPIX/128), 256>>>();
    k_wattn <<<2048, 256, wattn_smem>>>(rpb);
    k_proj_b<<<dim3(3, NPIX/128), 256>>>(proj_b);
    k_ln2   <<<NPIX/8, 256>>>(n2w, n2b);
    k_pin_b <<<dim3(8, NPIX/128), 256>>>();
    k_dw    <<<dim3(BATCH*HH*(WW/4), 2), 256>>>(dw_w);
    k_pout_b<<<dim3(3, NPIX/128), 256>>>(outp);
}

// round 8
// speedup vs baseline: 4.7080x; 1.4356x over previous
#include <cuda_runtime.h>
#include <cuda_bf16.h>
#include <stdint.h>
#include <math.h>

typedef unsigned int u32;

#define BATCH 2
#define C 192
#define HH 256
#define WW 256
#define HW (HH*WW)
#define NPIX (BATCH*HW)
#define NH 8
#define HD 24
#define WS 8
#define SS 4
#define HID 510
#define HID2 1020

// ---- scratch ----
__device__ float g_xt[NPIX*C];
__device__ float g_x2[NPIX*C];
__device__ __nv_bfloat16 g_xnb[(size_t)NPIX*C];
__device__ __nv_bfloat16 g_qkvb[(size_t)NPIX*576];
__device__ __nv_bfloat16 g_attnb[(size_t)NPIX*C];
__device__ __nv_bfloat16 g_ynb[(size_t)NPIX*C];
__device__ __nv_bfloat16 g_y[(size_t)NPIX*HID2];
__device__ __nv_bfloat16 g_gg[(size_t)NPIX*512];
__device__ __nv_bfloat16 g_qkvw[576*C];
__device__ __nv_bfloat16 g_projw[C*C];
__device__ __nv_bfloat16 g_pinb[HID2*C];
__device__ __nv_bfloat16 g_poutb[C*512];

__device__ __forceinline__ u32 sptr(const void* p) {
    return (u32)__cvta_generic_to_shared(p);
}
__device__ __forceinline__ void cpa16(u32 dst, const void* src, bool full) {
    int sz = full ? 16 : 0;
    asm volatile("cp.async.cg.shared.global [%0], [%1], 16, %2;" :: "r"(dst), "l"(src), "r"(sz));
}
__device__ __forceinline__ void ldsm4(u32& r0, u32& r1, u32& r2, u32& r3, u32 a) {
    asm volatile("ldmatrix.sync.aligned.m8n8.x4.shared.b16 {%0,%1,%2,%3}, [%4];"
        : "=r"(r0), "=r"(r1), "=r"(r2), "=r"(r3) : "r"(a));
}
__device__ __forceinline__ void ldsm4t(u32& r0, u32& r1, u32& r2, u32& r3, u32 a) {
    asm volatile("ldmatrix.sync.aligned.m8n8.x4.trans.shared.b16 {%0,%1,%2,%3}, [%4];"
        : "=r"(r0), "=r"(r1), "=r"(r2), "=r"(r3) : "r"(a));
}
__device__ __forceinline__ void mma_bf16(float& c0, float& c1, float& c2, float& c3,
    u32 a0, u32 a1, u32 a2, u32 a3, u32 b0, u32 b1) {
    asm volatile("mma.sync.aligned.m16n8k16.row.col.f32.bf16.bf16.f32 "
        "{%0,%1,%2,%3}, {%4,%5,%6,%7}, {%8,%9}, {%0,%1,%2,%3};"
        : "+f"(c0), "+f"(c1), "+f"(c2), "+f"(c3)
        : "r"(a0), "r"(a1), "r"(a2), "r"(a3), "r"(b0), "r"(b1));
}
__device__ __forceinline__ u32 packbf(float a, float b) {
    __nv_bfloat162 t = __floats2bfloat162_rn(a, b);
    return *(u32*)&t;
}

// ================= weight converts ==================
__global__ void k_cvt_qkvw(const float* __restrict__ src) {
    int i = blockIdx.x*256 + threadIdx.x;
    if (i < 576*C) {
        g_qkvw[i] = __float2bfloat16(src[i]);
    }
}
__global__ void k_cvt_projw(const float* __restrict__ src) {
    int i = blockIdx.x*256 + threadIdx.x;
    if (i < C*C) {
        g_projw[i] = __float2bfloat16(src[i]);
    }
}
__global__ void k_cvt_pin(const float* __restrict__ src) {
    int i = blockIdx.x*256 + threadIdx.x;
    if (i < HID2*C) {
        g_pinb[i] = __float2bfloat16(src[i]);
    }
}
__global__ void k_cvt_pout(const float* __restrict__ src) {
    int i = blockIdx.x*256 + threadIdx.x;
    if (i < C*512) {
        int o = i >> 9;
        int k = i & 511;
        g_poutb[i] = __float2bfloat16(k < HID ? src[o*HID + k] : 0.f);
    }
}

// ================= K1: LN1 + transpose + window-permuted bf16 ==================
__global__ __launch_bounds__(256) void k_ln1(const float* __restrict__ x,
        const float* __restrict__ w, const float* __restrict__ b) {
    __shared__ float s[C*33];
    __shared__ float smu[32];
    __shared__ float srv[32];
    __shared__ int slot_s[32];
    int pix0 = blockIdx.x * 32;
    int bb = pix0 / HW;
    int hw0 = pix0 % HW;
    for (int e = threadIdx.x; e < C*32; e += 256) {
        int c = e >> 5;
        int p = e & 31;
        s[c*33 + p] = x[(size_t)(bb*C + c)*HW + hw0 + p];
    }
    __syncthreads();
    if (threadIdx.x < 32) {
        int p = threadIdx.x;
        float sum = 0.f;
        float sq = 0.f;
        for (int c = 0; c < C; c++) {
            float v = s[c*33+p];
            sum += v;
            sq += v*v;
        }
        float mu = sum / C;
        float var = sq / C - mu*mu;
        smu[p] = mu;
        srv[p] = rsqrtf(var + 1e-5f);
        int hw = hw0 + p;
        int r = hw >> 8;
        int cc = hw & 255;
        int sr = (r - SS + 256) & 255;
        int sc = (cc - SS + 256) & 255;
        slot_s[p] = (((bb << 10) + ((sr >> 3) << 5) + (sc >> 3)) << 6) + ((sr & 7) << 3) + (sc & 7);
    }
    __syncthreads();
    for (int e = threadIdx.x; e < C*32; e += 256) {
        int p = e / C;
        int c = e % C;
        float v = s[c*33 + p];
        g_xt[(pix0 + p)*C + c] = v;
        float ln = (v - smu[p]) * srv[p] * w[c] + b[c];
        g_xnb[(size_t)slot_s[p]*C + c] = __float2bfloat16(ln);
    }
}

// ================= tile loaders ==================
__device__ __forceinline__ void qkv_load(__nv_bfloat16* Adst, __nv_bfloat16* Bdst,
                                         int pt, int ot, int k0, int tid) {
    #pragma unroll
    for (int i = 0; i < 2; i++) {
        int e = tid + i*256;
        int row = e >> 2;
        int seg = e & 3;
        cpa16(sptr(Adst + row*40 + seg*8), g_xnb + (size_t)(pt + row)*C + k0 + seg*8, true);
        int og = ot + row;
        bool ok = og < 576;
        cpa16(sptr(Bdst + row*40 + seg*8), g_qkvw + (size_t)(ok ? og : 0)*C + k0 + seg*8, ok);
    }
    asm volatile("cp.async.commit_group;" ::: "memory");
}

__device__ __forceinline__ void proj_load(__nv_bfloat16* Adst, __nv_bfloat16* Bdst,
                                          int pt, int ct, int k0, int tid) {
    #pragma unroll
    for (int i = 0; i < 2; i++) {
        int e = tid + i*256;
        int row = e >> 2;
        int seg = e & 3;
        cpa16(sptr(Adst + row*40 + seg*8), g_attnb + (size_t)(pt + row)*C + k0 + seg*8, true);
    }
    int row = tid >> 2;
    int seg = tid & 3;
    cpa16(sptr(Bdst + row*40 + seg*8), g_projw + (size_t)(ct + row)*C + k0 + seg*8, true);
    asm volatile("cp.async.commit_group;" ::: "memory");
}

__device__ __forceinline__ void pin_load(__nv_bfloat16* Adst, __nv_bfloat16* Bdst,
                                         int pt, int ot, int k0, int tid) {
    #pragma unroll
    for (int i = 0; i < 2; i++) {
        int e = tid + i*256;
        int row = e >> 2;
        int seg = e & 3;
        cpa16(sptr(Adst + row*40 + seg*8), g_ynb + (size_t)(pt + row)*C + k0 + seg*8, true);
        int og = ot + row;
        bool ok = og < HID2;
        cpa16(sptr(Bdst + row*40 + seg*8), g_pinb + (size_t)(ok ? og : 0)*C + k0 + seg*8, ok);
    }
    asm volatile("cp.async.commit_group;" ::: "memory");
}

__device__ __forceinline__ void pout_load(__nv_bfloat16* Adst, __nv_bfloat16* Bdst,
                                          int pt, int ct, int k0, int tid) {
    #pragma unroll
    for (int i = 0; i < 2; i++) {
        int e = tid + i*256;
        int row = e >> 2;
        int seg = e & 3;
        cpa16(sptr(Adst + row*40 + seg*8), g_gg + (size_t)(pt + row)*512 + k0 + seg*8, true);
    }
    int row = tid >> 2;
    int seg = tid & 3;
    cpa16(sptr(Bdst + row*40 + seg*8), g_poutb + (size_t)(ct + row)*512 + k0 + seg*8, true);
    asm volatile("cp.async.commit_group;" ::: "memory");
}

// ================= K2a: QKV GEMM bf16 (131072 x 576 x 192) -> bf16 ==================
__global__ __launch_bounds__(256,2) void k_qkv_b() {
    __shared__ __align__(16) __nv_bfloat16 As[2][5120];
    __shared__ __align__(16) __nv_bfloat16 Bs[2][5120];
    int pt = blockIdx.y*128;
    int ot = blockIdx.x*128;
    int tid = threadIdx.x;
    int lane = tid & 31;
    int warp = tid >> 5;
    int m0 = (warp >> 2)*64;
    int n0 = (warp & 3)*32;
    float acc[4][4][4] = {};

    qkv_load(As[0], Bs[0], pt, ot, 0, tid);

    for (int ch = 0; ch < 6; ch++) {
        asm volatile("cp.async.wait_group 0;" ::: "memory");
        __syncthreads();
        if (ch < 5) {
            qkv_load(As[(ch+1)&1], Bs[(ch+1)&1], pt, ot, (ch+1)*32, tid);
        }
        u32 ab = sptr(As[ch & 1]);
        u32 bbs = sptr(Bs[ch & 1]);
        #pragma unroll
        for (int ks = 0; ks < 2; ks++) {
            u32 av[4][4];
            u32 bv[4][2];
            #pragma unroll
            for (int mt = 0; mt < 4; mt++) {
                int row = m0 + mt*16 + (lane & 15);
                u32 ad = ab + (row*40 + ((lane >> 4) & 1)*8 + ks*16)*2;
                ldsm4(av[mt][0], av[mt][1], av[mt][2], av[mt][3], ad);
            }
            #pragma unroll
            for (int n2 = 0; n2 < 2; n2++) {
                int row = n0 + n2*16 + (lane & 7) + ((lane >> 4) & 1)*8;
                u32 ad = bbs + (row*40 + ((lane >> 3) & 1)*8 + ks*16)*2;
                u32 r0;
                u32 r1;
                u32 r2;
                u32 r3;
                ldsm4(r0, r1, r2, r3, ad);
                bv[n2*2+0][0] = r0;
                bv[n2*2+0][1] = r1;
                bv[n2*2+1][0] = r2;
                bv[n2*2+1][1] = r3;
            }
            #pragma unroll
            for (int mt = 0; mt < 4; mt++) {
                #pragma unroll
                for (int nt = 0; nt < 4; nt++) {
                    mma_bf16(acc[mt][nt][0], acc[mt][nt][1], acc[mt][nt][2], acc[mt][nt][3],
                             av[mt][0], av[mt][1], av[mt][2], av[mt][3], bv[nt][0], bv[nt][1]);
                }
            }
        }
    }

    const float qscale = 0.20412414523193154f;
    int lr = lane >> 2;
    int lc = lane & 3;
    #pragma unroll
    for (int mt = 0; mt < 4; mt++) {
        int row = pt + m0 + mt*16 + lr;
        #pragma unroll
        for (int nt = 0; nt < 4; nt++) {
            int col = ot + n0 + nt*8 + 2*lc;
            if (col < 576) {
                float s = (col < C) ? qscale : 1.f;
                __nv_bfloat162 v0;
                v0.x = __float2bfloat16(acc[mt][nt][0] * s);
                v0.y = __float2bfloat16(acc[mt][nt][1] * s);
                *(__nv_bfloat162*)&g_qkvb[(size_t)row*576 + col] = v0;
                __nv_bfloat162 v1;
                v1.x = __float2bfloat16(acc[mt][nt][2] * s);
                v1.y = __float2bfloat16(acc[mt][nt][3] * s);
                *(__nv_bfloat162*)&g_qkvb[(size_t)(row+8)*576 + col] = v1;
            }
        }
    }
}

// ================= K2b: tensor-core window attention ==================
// smem row: [Q 8 heads x 32 | K 8 heads x 32 | V 8 heads x 32], stride 776 bf16
#define SW 776
__global__ __launch_bounds__(128,2) void k_wattn_t(const float* __restrict__ rpb) {
    extern __shared__ __nv_bfloat16 smw[];
    __shared__ float rpb_s[225*NH];
    __shared__ int lab[64];

    int tid = threadIdx.x;
    int lane = tid & 31;
    int warp = tid >> 5;
    int widx = blockIdx.x;
    int pix0 = widx * 64;
    int wy = (widx >> 5) & 31;
    int wx = widx & 31;

    if (tid < 64) {
        int i1 = tid >> 3;
        int j1 = tid & 7;
        int sr = wy*8 + i1;
        int sc = wx*8 + j1;
        lab[tid] = ((sr >= HH-WS) + (sr >= HH-SS))*3 + ((sc >= WW-WS) + (sc >= WW-SS));
    }
    for (int e = tid; e < 225*NH; e += 128) {
        rpb_s[e] = rpb[e];
    }
    // zero the K-dim pads of Q and K regions (16B each)
    for (int e = tid; e < 1024; e += 128) {
        int row = e >> 4;
        int reg = e & 15;
        int col = (reg < 8) ? (reg*32 + 24) : (256 + (reg - 8)*32 + 24);
        *(float4*)&smw[row*SW + col] = make_float4(0.f, 0.f, 0.f, 0.f);
    }
    // stage QKV (rearranged to padded per-head layout)
    for (int e = tid; e < 4608; e += 128) {
        int row = e / 72;
        int t = e - row*72;
        int sec = t / 24;
        int t2 = t - sec*24;
        int h = t2 / 3;
        int cs = (t2 - h*3)*8;
        int srccol = sec*192 + h*24 + cs;
        int dstcol = sec*256 + h*32 + cs;
        cpa16(sptr(&smw[row*SW + dstcol]), g_qkvb + (size_t)(pix0 + row)*576 + srccol, true);
    }
    asm volatile("cp.async.commit_group;" ::: "memory");
    asm volatile("cp.async.wait_group 0;" ::: "memory");
    __syncthreads();

    int lr = lane >> 2;
    int lc = lane & 3;
    int wrow0 = warp*16;
    int r0 = wrow0 + lr;
    int r1 = r0 + 8;
    // rpb address bases: idx*8 = base - 120*f (col B: -8)
    int baseA = (((r0 >> 3) + 7)*15 + ((r0 & 7) - 2*lc + 7))*8;
    int baseB = (((r1 >> 3) + 7)*15 + ((r1 & 7) - 2*lc + 7))*8;
    int labA = lab[r0];
    int labB = lab[r1];
    u32 mbits = 0;
    #pragma unroll
    for (int f = 0; f < 8; f++) {
        int cA = f*8 + 2*lc;
        int lA = lab[cA];
        int lB = lab[cA + 1];
        if (labA != lA) { mbits |= 1u << (f*4 + 0); }
        if (labA != lB) { mbits |= 1u << (f*4 + 1); }
        if (labB != lA) { mbits |= 1u << (f*4 + 2); }
        if (labB != lB) { mbits |= 1u << (f*4 + 3); }
    }

    u32 smbase = sptr(smw);
    for (int h = 0; h < NH; h++) {
        float c[8][4];
        #pragma unroll
        for (int f = 0; f < 8; f++) {
            c[f][0] = 0.f; c[f][1] = 0.f; c[f][2] = 0.f; c[f][3] = 0.f;
        }
        #pragma unroll
        for (int ks = 0; ks < 2; ks++) {
            u32 aq[4];
            u32 ad = smbase + ((wrow0 + (lane & 15))*SW + h*32 + ((lane >> 4) & 1)*8 + ks*16)*2;
            ldsm4(aq[0], aq[1], aq[2], aq[3], ad);
            #pragma unroll
            for (int n2 = 0; n2 < 4; n2++) {
                u32 b0;
                u32 b1;
                u32 b2;
                u32 b3;
                u32 bd = smbase + ((n2*16 + (lane & 7) + ((lane >> 4) & 1)*8)*SW
                                   + 256 + h*32 + ((lane >> 3) & 1)*8 + ks*16)*2;
                ldsm4(b0, b1, b2, b3, bd);
                mma_bf16(c[2*n2][0], c[2*n2][1], c[2*n2][2], c[2*n2][3],
                         aq[0], aq[1], aq[2], aq[3], b0, b1);
                mma_bf16(c[2*n2+1][0], c[2*n2+1][1], c[2*n2+1][2], c[2*n2+1][3],
                         aq[0], aq[1], aq[2], aq[3], b2, b3);
            }
        }
        // bias + mask
        int hA = baseA + h;
        int hB = baseB + h;
        #pragma unroll
        for (int f = 0; f < 8; f++) {
            c[f][0] += rpb_s[hA - 120*f]     + (((mbits >> (f*4+0)) & 1) ? -100.f : 0.f);
            c[f][1] += rpb_s[hA - 120*f - 8] + (((mbits >> (f*4+1)) & 1) ? -100.f : 0.f);
            c[f][2] += rpb_s[hB - 120*f]     + (((mbits >> (f*4+2)) & 1) ? -100.f : 0.f);
            c[f][3] += rpb_s[hB - 120*f - 8] + (((mbits >> (f*4+3)) & 1) ? -100.f : 0.f);
        }
        // softmax (rows r0: c[f][0..1], r1: c[f][2..3]) across quad lanes
        float mx0 = -1e30f;
        float mx1 = -1e30f;
        #pragma unroll
        for (int f = 0; f < 8; f++) {
            mx0 = fmaxf(mx0, fmaxf(c[f][0], c[f][1]));
            mx1 = fmaxf(mx1, fmaxf(c[f][2], c[f][3]));
        }
        mx0 = fmaxf(mx0, __shfl_xor_sync(0xffffffffu, mx0, 1));
        mx0 = fmaxf(mx0, __shfl_xor_sync(0xffffffffu, mx0, 2));
        mx1 = fmaxf(mx1, __shfl_xor_sync(0xffffffffu, mx1, 1));
        mx1 = fmaxf(mx1, __shfl_xor_sync(0xffffffffu, mx1, 2));
        float s0 = 0.f;
        float s1 = 0.f;
        #pragma unroll
        for (int f = 0; f < 8; f++) {
            c[f][0] = __expf(c[f][0] - mx0);
            c[f][1] = __expf(c[f][1] - mx0);
            c[f][2] = __expf(c[f][2] - mx1);
            c[f][3] = __expf(c[f][3] - mx1);
            s0 += c[f][0] + c[f][1];
            s1 += c[f][2] + c[f][3];
        }
        s0 += __shfl_xor_sync(0xffffffffu, s0, 1);
        s0 += __shfl_xor_sync(0xffffffffu, s0, 2);
        s1 += __shfl_xor_sync(0xffffffffu, s1, 1);
        s1 += __shfl_xor_sync(0xffffffffu, s1, 2);
        float inv0 = 1.f / s0;
        float inv1 = 1.f / s1;
        // pack P into A-fragments (bf16), folding normalization
        u32 ap[4][4];
        #pragma unroll
        for (int j = 0; j < 4; j++) {
            ap[j][0] = packbf(c[2*j][0]*inv0,   c[2*j][1]*inv0);
            ap[j][1] = packbf(c[2*j][2]*inv1,   c[2*j][3]*inv1);
            ap[j][2] = packbf(c[2*j+1][0]*inv0, c[2*j+1][1]*inv0);
            ap[j][3] = packbf(c[2*j+1][2]*inv1, c[2*j+1][3]*inv1);
        }
        // AV: B frags from V via trans ldmatrix
        float o[3][4];
        #pragma unroll
        for (int nt = 0; nt < 3; nt++) {
            o[nt][0] = 0.f; o[nt][1] = 0.f; o[nt][2] = 0.f; o[nt][3] = 0.f;
        }
        #pragma unroll
        for (int j = 0; j < 4; j++) {
            u32 lo0; u32 lo1; u32 lo2; u32 lo3;
            u32 hi0; u32 hi1; u32 hi2; u32 hi3;
            u32 vlo = smbase + ((j*16 + (lane & 7))*SW + 512 + h*32 + (lane >> 3)*8)*2;
            u32 vhi = smbase + ((j*16 + 8 + (lane & 7))*SW + 512 + h*32 + (lane >> 3)*8)*2;
            ldsm4t(lo0, lo1, lo2, lo3, vlo);
            ldsm4t(hi0, hi1, hi2, hi3, vhi);
            mma_bf16(o[0][0], o[0][1], o[0][2], o[0][3], ap[j][0], ap[j][1], ap[j][2], ap[j][3], lo0, hi0);
            mma_bf16(o[1][0], o[1][1], o[1][2], o[1][3], ap[j][0], ap[j][1], ap[j][2], ap[j][3], lo1, hi1);
            mma_bf16(o[2][0], o[2][1], o[2][2], o[2][3], ap[j][0], ap[j][1], ap[j][2], ap[j][3], lo2, hi2);
        }
        #pragma unroll
        for (int nt = 0; nt < 3; nt++) {
            int col = h*24 + nt*8 + 2*lc;
            __nv_bfloat162 v0;
            v0.x = __float2bfloat16(o[nt][0]);
            v0.y = __float2bfloat16(o[nt][1]);
            *(__nv_bfloat162*)&g_attnb[(size_t)(pix0 + r0)*C + col] = v0;
            __nv_bfloat162 v1;
            v1.x = __float2bfloat16(o[nt][2]);
            v1.y = __float2bfloat16(o[nt][3]);
            *(__nv_bfloat162*)&g_attnb[(size_t)(pix0 + r1)*C + col] = v1;
        }
    }
}

// ================= K2c: proj GEMM bf16 (131072 x 192 x 192) + bias + residual ==================
__global__ __launch_bounds__(256,2) void k_proj_b(const float* __restrict__ pb) {
    __shared__ __align__(16) __nv_bfloat16 As[2][5120];
    __shared__ __align__(16) __nv_bfloat16 Bs[2][2560];
    int pt = blockIdx.y*128;
    int ct = blockIdx.x*64;
    int tid = threadIdx.x;
    int lane = tid & 31;
    int warp = tid >> 5;
    int m0 = (warp & 3)*32;
    int n0 = (warp >> 2)*32;
    float acc[2][4][4] = {};

    proj_load(As[0], Bs[0], pt, ct, 0, tid);

    for (int ch = 0; ch < 6; ch++) {
        asm volatile("cp.async.wait_group 0;" ::: "memory");
        __syncthreads();
        if (ch < 5) {
            proj_load(As[(ch+1)&1], Bs[(ch+1)&1], pt, ct, (ch+1)*32, tid);
        }
        u32 ab = sptr(As[ch & 1]);
        u32 bbs = sptr(Bs[ch & 1]);
        #pragma unroll
        for (int ks = 0; ks < 2; ks++) {
            u32 av[2][4];
            u32 bv[4][2];
            #pragma unroll
            for (int mt = 0; mt < 2; mt++) {
                int row = m0 + mt*16 + (lane & 15);
                u32 ad = ab + (row*40 + ((lane >> 4) & 1)*8 + ks*16)*2;
                ldsm4(av[mt][0], av[mt][1], av[mt][2], av[mt][3], ad);
            }
            #pragma unroll
            for (int n2 = 0; n2 < 2; n2++) {
                int row = n0 + n2*16 + (lane & 7) + ((lane >> 4) & 1)*8;
                u32 ad = bbs + (row*40 + ((lane >> 3) & 1)*8 + ks*16)*2;
                u32 r0;
                u32 r1;
                u32 r2;
                u32 r3;
                ldsm4(r0, r1, r2, r3, ad);
                bv[n2*2+0][0] = r0;
                bv[n2*2+0][1] = r1;
                bv[n2*2+1][0] = r2;
                bv[n2*2+1][1] = r3;
            }
            #pragma unroll
            for (int mt = 0; mt < 2; mt++) {
                #pragma unroll
                for (int nt = 0; nt < 4; nt++) {
                    mma_bf16(acc[mt][nt][0], acc[mt][nt][1], acc[mt][nt][2], acc[mt][nt][3],
                             av[mt][0], av[mt][1], av[mt][2], av[mt][3], bv[nt][0], bv[nt][1]);
                }
            }
        }
    }

    int lr = lane >> 2;
    int lc = lane & 3;
    #pragma unroll
    for (int mt = 0; mt < 2; mt++) {
        #pragma unroll
        for (int half = 0; half < 2; half++) {
            int row = pt + m0 + mt*16 + lr + half*8;
            int bb = row >> 16;
            int widx = (row >> 6) & 1023;
            int tok = row & 63;
            int r = (((widx >> 5) << 3) + (tok >> 3) + SS) & 255;
            int c2 = (((widx & 31) << 3) + (tok & 7) + SS) & 255;
            int gbase = ((bb*HH + r)*WW + c2)*C;
            #pragma unroll
            for (int nt = 0; nt < 4; nt++) {
                int col = ct + n0 + nt*8 + 2*lc;
                float2 v;
                v.x = acc[mt][nt][half*2+0] + pb[col] + g_xt[gbase + col];
                v.y = acc[mt][nt][half*2+1] + pb[col+1] + g_xt[gbase + col + 1];
                *(float2*)&g_x2[gbase + col] = v;
            }
        }
    }
}

// ================= K3: LN2 -> bf16 ==================
__global__ __launch_bounds__(256) void k_ln2(const float* __restrict__ w,
                                             const float* __restrict__ b) {
    int pix = blockIdx.x*8 + (threadIdx.x >> 5);
    int lane = threadIdx.x & 31;
    const float* row = g_x2 + (size_t)pix*C;
    float v[6];
    float sum = 0.f;
    float sq = 0.f;
    #pragma unroll
    for (int i = 0; i < 6; i++) {
        v[i] = row[lane + 32*i];
        sum += v[i];
        sq += v[i]*v[i];
    }
    #pragma unroll
    for (int o = 16; o; o >>= 1) {
        sum += __shfl_xor_sync(0xffffffffu, sum, o);
        sq  += __shfl_xor_sync(0xffffffffu, sq, o);
    }
    float mu = sum / C;
    float rv = rsqrtf(sq / C - mu*mu + 1e-5f);
    __nv_bfloat16* outp = g_ynb + (size_t)pix*C;
    #pragma unroll
    for (int i = 0; i < 6; i++) {
        int c = lane + 32*i;
        outp[c] = __float2bfloat16((v[i]-mu)*rv*w[c] + b[c]);
    }
}

// ================= K4: pin GEMM bf16 (131072 x 1020 x 192) ==================
__global__ __launch_bounds__(256,2) void k_pin_b() {
    __shared__ __align__(16) __nv_bfloat16 As[2][5120];
    __shared__ __align__(16) __nv_bfloat16 Bs[2][5120];
    int pt = blockIdx.y*128;
    int ot = blockIdx.x*128;
    int tid = threadIdx.x;
    int lane = tid & 31;
    int warp = tid >> 5;
    int m0 = (warp >> 2)*64;
    int n0 = (warp & 3)*32;
    float acc[4][4][4] = {};

    pin_load(As[0], Bs[0], pt, ot, 0, tid);

    for (int ch = 0; ch < 6; ch++) {
        asm volatile("cp.async.wait_group 0;" ::: "memory");
        __syncthreads();
        if (ch < 5) {
            pin_load(As[(ch+1)&1], Bs[(ch+1)&1], pt, ot, (ch+1)*32, tid);
        }
        u32 ab = sptr(As[ch & 1]);
        u32 bbs = sptr(Bs[ch & 1]);
        #pragma unroll
        for (int ks = 0; ks < 2; ks++) {
            u32 av[4][4];
            u32 bv[4][2];
            #pragma unroll
            for (int mt = 0; mt < 4; mt++) {
                int row = m0 + mt*16 + (lane & 15);
                u32 ad = ab + (row*40 + ((lane >> 4) & 1)*8 + ks*16)*2;
                ldsm4(av[mt][0], av[mt][1], av[mt][2], av[mt][3], ad);
            }
            #pragma unroll
            for (int n2 = 0; n2 < 2; n2++) {
                int row = n0 + n2*16 + (lane & 7) + ((lane >> 4) & 1)*8;
                u32 ad = bbs + (row*40 + ((lane >> 3) & 1)*8 + ks*16)*2;
                u32 r0;
                u32 r1;
                u32 r2;
                u32 r3;
                ldsm4(r0, r1, r2, r3, ad);
                bv[n2*2+0][0] = r0;
                bv[n2*2+0][1] = r1;
                bv[n2*2+1][0] = r2;
                bv[n2*2+1][1] = r3;
            }
            #pragma unroll
            for (int mt = 0; mt < 4; mt++) {
                #pragma unroll
                for (int nt = 0; nt < 4; nt++) {
                    mma_bf16(acc[mt][nt][0], acc[mt][nt][1], acc[mt][nt][2], acc[mt][nt][3],
                             av[mt][0], av[mt][1], av[mt][2], av[mt][3], bv[nt][0], bv[nt][1]);
                }
            }
        }
    }

    int lr = lane >> 2;
    int lc = lane & 3;
    #pragma unroll
    for (int mt = 0; mt < 4; mt++) {
        int row = pt + m0 + mt*16 + lr;
        #pragma unroll
        for (int nt = 0; nt < 4; nt++) {
            int col = ot + n0 + nt*8 + 2*lc;
            if (col < HID2) {
                __nv_bfloat162 v0;
                v0.x = __float2bfloat16(acc[mt][nt][0]);
                v0.y = __float2bfloat16(acc[mt][nt][1]);
                *(__nv_bfloat162*)&g_y[(size_t)row*HID2 + col] = v0;
                __nv_bfloat162 v1;
                v1.x = __float2bfloat16(acc[mt][nt][2]);
                v1.y = __float2bfloat16(acc[mt][nt][3]);
                *(__nv_bfloat162*)&g_y[(size_t)(row+8)*HID2 + col] = v1;
            }
        }
    }
}

// ================= K5: depthwise 3x3 + gated GELU (bf16 in/out) ==================
__global__ __launch_bounds__(256) void k_dw(const float* __restrict__ dw) {
    int bx = blockIdx.x;
    int c = blockIdx.y * 256 + threadIdx.x;
    int xseg = (bx & 63) * 4;
    int r = (bx >> 6) & 255;
    int bb = bx >> 14;
    if (blockIdx.y == 0 && threadIdx.x < 2) {
        #pragma unroll
        for (int o = 0; o < 4; o++) {
            g_gg[((size_t)(bb*HH + r)*WW + xseg + o)*512 + HID + threadIdx.x] = __float2bfloat16(0.f);
        }
    }
    if (c >= HID) {
        return;
    }
    float ya[3][6];
    float yb[3][6];
    #pragma unroll
    for (int dy = 0; dy < 3; dy++) {
        int rowi = r + dy - 1;
        bool rok = (unsigned)rowi < 256u;
        #pragma unroll
        for (int dx = 0; dx < 6; dx++) {
            int col = xseg + dx - 1;
            bool ok = rok && ((unsigned)col < 256u);
            size_t base = ((size_t)(bb*HH + rowi)*WW + col)*HID2;
            ya[dy][dx] = ok ? __bfloat162float(g_y[base + c]) : 0.f;
            yb[dy][dx] = ok ? __bfloat162float(g_y[base + c + HID]) : 0.f;
        }
    }
    float wa[9];
    float wb[9];
    #pragma unroll
    for (int t = 0; t < 9; t++) {
        wa[t] = dw[c*9 + t];
        wb[t] = dw[(c + HID)*9 + t];
    }
    #pragma unroll
    for (int o = 0; o < 4; o++) {
        float a = 0.f;
        float g2 = 0.f;
        #pragma unroll
        for (int ky = 0; ky < 3; ky++) {
            #pragma unroll
            for (int kx = 0; kx < 3; kx++) {
                a  += wa[ky*3+kx] * ya[ky][o+kx];
                g2 += wb[ky*3+kx] * yb[ky][o+kx];
            }
        }
        float ge = 0.5f * a * (1.f + erff(a * 0.70710678118654752f));
        g_gg[((size_t)(bb*HH + r)*WW + xseg + o)*512 + c] = __float2bfloat16(ge * g2);
    }
}

// ================= K6: pout GEMM bf16 (131072 x 192 x 512) + residual -> NCHW ==================
#define SPP 132
__global__ __launch_bounds__(256,2) void k_pout_b(float* __restrict__ outp) {
    __shared__ __align__(16) float smem_f[8448];
    __nv_bfloat16* As = (__nv_bfloat16*)smem_f;
    __nv_bfloat16* Bs = (__nv_bfloat16*)(smem_f + 5120);
    float* Cs = smem_f;
    int pt = blockIdx.y*128;
    int ct = blockIdx.x*64;
    int tid = threadIdx.x;
    int lane = tid & 31;
    int warp = tid >> 5;
    int m0 = (warp & 3)*32;
    int n0 = (warp >> 2)*32;
    float acc[2][4][4] = {};

    pout_load(As, Bs, pt, ct, 0, tid);

    for (int ch = 0; ch < 16; ch++) {
        asm volatile("cp.async.wait_group 0;" ::: "memory");
        __syncthreads();
        if (ch < 15) {
            int st = (ch+1) & 1;
            pout_load(As + st*5120, Bs + st*2560, pt, ct, (ch+1)*32, tid);
        }
        u32 ab = sptr(As + (ch & 1)*5120);
        u32 bbs = sptr(Bs + (ch & 1)*2560);
        #pragma unroll
        for (int ks = 0; ks < 2; ks++) {
            u32 av[2][4];
            u32 bv[4][2];
            #pragma unroll
            for (int mt = 0; mt < 2; mt++) {
                int row = m0 + mt*16 + (lane & 15);
                u32 ad = ab + (row*40 + ((lane >> 4) & 1)*8 + ks*16)*2;
                ldsm4(av[mt][0], av[mt][1], av[mt][2], av[mt][3], ad);
            }
            #pragma unroll
            for (int n2 = 0; n2 < 2; n2++) {
                int row = n0 + n2*16 + (lane & 7) + ((lane >> 4) & 1)*8;
                u32 ad = bbs + (row*40 + ((lane >> 3) & 1)*8 + ks*16)*2;
                u32 r0;
                u32 r1;
                u32 r2;
                u32 r3;
                ldsm4(r0, r1, r2, r3, ad);
                bv[n2*2+0][0] = r0;
                bv[n2*2+0][1] = r1;
                bv[n2*2+1][0] = r2;
                bv[n2*2+1][1] = r3;
            }
            #pragma unroll
            for (int mt = 0; mt < 2; mt++) {
                #pragma unroll
                for (int nt = 0; nt < 4; nt++) {
                    mma_bf16(acc[mt][nt][0], acc[mt][nt][1], acc[mt][nt][2], acc[mt][nt][3],
                             av[mt][0], av[mt][1], av[mt][2], av[mt][3], bv[nt][0], bv[nt][1]);
                }
            }
        }
    }
    __syncthreads();

    int lr = lane >> 2;
    int lc = lane & 3;
    #pragma unroll
    for (int mt = 0; mt < 2; mt++) {
        int row = m0 + mt*16 + lr;
        #pragma unroll
        for (int nt = 0; nt < 4; nt++) {
            int col = n0 + nt*8 + 2*lc;
            Cs[col*SPP + row] = acc[mt][nt][0];
            Cs[(col+1)*SPP + row] = acc[mt][nt][1];
            Cs[col*SPP + row + 8] = acc[mt][nt][2];
            Cs[(col+1)*SPP + row + 8] = acc[mt][nt][3];
        }
    }
    __syncthreads();
    for (int e = tid; e < 2048; e += 256) {
        int p = e >> 4;
        int c4 = e & 15;
        float4 v = *(const float4*)&g_x2[(size_t)(pt + p)*C + ct + c4*4];
        Cs[(c4*4+0)*SPP + p] += v.x;
        Cs[(c4*4+1)*SPP + p] += v.y;
        Cs[(c4*4+2)*SPP + p] += v.z;
        Cs[(c4*4+3)*SPP + p] += v.w;
    }
    __syncthreads();
    int bb = pt >> 16;
    int hw0 = pt & 65535;
    for (int e = tid; e < 2048; e += 256) {
        int c = e >> 5;
        int p4 = e & 31;
        float4 v = *(const float4*)&Cs[c*SPP + p4*4];
        *(float4*)&outp[((size_t)(bb*C + ct + c))*HW + hw0 + p4*4] = v;
    }
}

// ================= launch ==================
extern "C" void kernel_launch(void* const* d_in, const int* in_sizes, int n_in,
                              void* d_out, int out_size) {
    const float* x      = (const float*)d_in[0];
    const float* n1w    = (const float*)d_in[1];
    const float* n1b    = (const float*)d_in[2];
    const float* qkv_w  = (const float*)d_in[3];
    const float* rpb    = (const float*)d_in[4];
    const float* proj_w = (const float*)d_in[5];
    const float* proj_b = (const float*)d_in[6];
    const float* n2w    = (const float*)d_in[7];
    const float* n2b    = (const float*)d_in[8];
    const float* pin_w  = (const float*)d_in[9];
    const float* dw_w   = (const float*)d_in[10];
    const float* pout_w = (const float*)d_in[11];
    float* outp = (float*)d_out;

    const int wattn_smem = 64*SW*2;   // 99328
    cudaFuncSetAttribute(k_wattn_t, cudaFuncAttributeMaxDynamicSharedMemorySize, wattn_smem);

    k_cvt_qkvw<<<(576*C + 255)/256, 256>>>(qkv_w);
    k_cvt_projw<<<(C*C + 255)/256, 256>>>(proj_w);
    k_cvt_pin<<<(HID2*C + 255)/256, 256>>>(pin_w);
    k_cvt_pout<<<(C*512 + 255)/256, 256>>>(pout_w);
    k_ln1    <<<NPIX/32, 256>>>(x, n1w, n1b);
    k_qkv_b  <<<dim3(5, NPIX/128), 256>>>();
    k_wattn_t<<<2048, 128, wattn_smem>>>(rpb);
    k_proj_b <<<dim3(3, NPIX/128), 256>>>(proj_b);
    k_ln2    <<<NPIX/8, 256>>>(n2w, n2b);
    k_pin_b  <<<dim3(8, NPIX/128), 256>>>();
    k_dw     <<<dim3(BATCH*HH*(WW/4), 2), 256>>>(dw_w);
    k_pout_b <<<dim3(3, NPIX/128), 256>>>(outp);
}